// round 9
// baseline (speedup 1.0000x reference)
#include <cuda_runtime.h>
#include <cuda_fp16.h>
#include <cstdint>

// Problem constants
#define D_IN   1024
#define NSEQ   2048
#define BATCH  4
#define NHEAD  16
#define HDIM   64
#define MTOT   (BATCH*NSEQ)   // 8192
#define GK     1024
#define NQKV   3072

// ---------------------------------------------------------------------------
// Scratch (no cudaMalloc allowed)
// ---------------------------------------------------------------------------
__device__ __half g_Xh[(size_t)MTOT * D_IN];
__device__ __half g_Xl[(size_t)MTOT * D_IN];
__device__ __half g_Ch[(size_t)MTOT * D_IN];
__device__ __half g_Cl[(size_t)MTOT * D_IN];
__device__ __half g_Wth[(size_t)NQKV * D_IN];
__device__ __half g_Wtl[(size_t)NQKV * D_IN];
__device__ __half g_Qh[(size_t)MTOT * D_IN];
__device__ __half g_Ql[(size_t)MTOT * D_IN];
__device__ __half g_Kh[(size_t)MTOT * D_IN];
__device__ __half g_Kl[(size_t)MTOT * D_IN];
__device__ __half g_Vth[(size_t)BATCH * NHEAD * HDIM * NSEQ];   // hi only

__device__ __forceinline__ float fexp2(float x) {
    float r;
    asm("ex2.approx.f32 %0, %1;" : "=f"(r) : "f"(x));
    return r;
}
__device__ __forceinline__ uint32_t smem_u32(const void* p) {
    uint32_t a;
    asm("{ .reg .u64 t; cvta.to.shared.u64 t, %1; cvt.u32.u64 %0, t; }" : "=r"(a) : "l"(p));
    return a;
}
__device__ __forceinline__ void cp16(uint32_t saddr, const void* gptr) {
    asm volatile("cp.async.cg.shared.global [%0], [%1], 16;" :: "r"(saddr), "l"(gptr));
}
__device__ __forceinline__ void ldsm4(uint32_t* r, uint32_t saddr) {
    asm volatile("ldmatrix.sync.aligned.m8n8.x4.shared.b16 {%0,%1,%2,%3}, [%4];"
        : "=r"(r[0]), "=r"(r[1]), "=r"(r[2]), "=r"(r[3]) : "r"(saddr));
}
__device__ __forceinline__ void mma_f16(float* c, const uint32_t* a,
                                        uint32_t b0, uint32_t b1)
{
    asm volatile(
        "mma.sync.aligned.m16n8k16.row.col.f32.f16.f16.f32 "
        "{%0,%1,%2,%3}, {%4,%5,%6,%7}, {%8,%9}, {%0,%1,%2,%3};"
        : "+f"(c[0]), "+f"(c[1]), "+f"(c[2]), "+f"(c[3])
        : "r"(a[0]), "r"(a[1]), "r"(a[2]), "r"(a[3]), "r"(b0), "r"(b1));
}

// ---------------------------------------------------------------------------
// Split fp32 -> fp16 hi + lo (used only for X)
// ---------------------------------------------------------------------------
__global__ __launch_bounds__(256) void split_kernel(
    const float* __restrict__ x, __half* __restrict__ hi,
    __half* __restrict__ lo)
{
    size_t i = (size_t)blockIdx.x * 256 + threadIdx.x;
    float4 v = ((const float4*)x)[i];
    __half h0 = __float2half_rn(v.x), h1 = __float2half_rn(v.y);
    __half h2 = __float2half_rn(v.z), h3 = __float2half_rn(v.w);
    __half l0 = __float2half_rn(v.x - __half2float(h0));
    __half l1 = __float2half_rn(v.y - __half2float(h1));
    __half l2 = __float2half_rn(v.z - __half2float(h2));
    __half l3 = __float2half_rn(v.w - __half2float(h3));
    __half2 hv0{h0, h1}, hv1{h2, h3}, lv0{l0, l1}, lv1{l2, l3};
    ((__half2*)hi)[i * 2 + 0] = hv0;
    ((__half2*)hi)[i * 2 + 1] = hv1;
    ((__half2*)lo)[i * 2 + 0] = lv0;
    ((__half2*)lo)[i * 2 + 1] = lv1;
}

// ---------------------------------------------------------------------------
// Transpose + split weights: W[K,1024] fp32 -> Wt[rowOff+N][K] fp16 hi/lo
// ---------------------------------------------------------------------------
__global__ __launch_bounds__(256) void transpose_split_kernel(
    const float* __restrict__ W, __half* __restrict__ Th,
    __half* __restrict__ Tl, int rowOff)
{
    __shared__ float t[32][33];
    int x0 = blockIdx.x * 32, y0 = blockIdx.y * 32;
    int tx = threadIdx.x, ty = threadIdx.y;  // (32, 8)
    #pragma unroll
    for (int j = 0; j < 32; j += 8)
        t[ty + j][tx] = W[(size_t)(y0 + ty + j) * D_IN + x0 + tx];
    __syncthreads();
    #pragma unroll
    for (int j = 0; j < 32; j += 8) {
        float v = t[tx][ty + j];
        __half h = __float2half_rn(v);
        size_t o = (size_t)(rowOff + x0 + ty + j) * GK + y0 + tx;
        Th[o] = h;
        Tl[o] = __float2half_rn(v - __half2float(h));
    }
}

// ---------------------------------------------------------------------------
// Pipelined split-fp16 GEMM, ldmatrix fragments, cp.async double buffering.
// MODE 0: out projection, 2-MMA (no Bl loads), fp32 out + bias.
// MODE 2: fused QKV; q/k regions 3-MMA -> split fp16; v region 2-MMA ->
//         transposed Vt hi via smem staging.
// ---------------------------------------------------------------------------
#define BK2 32
#define AS2 40
#define MAT_E (128 * AS2)
#define STG_E (4 * MAT_E)
#define GSMEM (2 * STG_E * 2)     // 81920 bytes
#define VT_STR 136

template<int MODE>
__global__ __launch_bounds__(256, 2) void gemm_ld_kernel(
    const __half* __restrict__ Ah_, const __half* __restrict__ Al_,
    const __half* __restrict__ Bh_, const __half* __restrict__ Bl_,
    const float* __restrict__ bias, float* __restrict__ C,
    __half* __restrict__ oQh, __half* __restrict__ oQl,
    __half* __restrict__ oKh, __half* __restrict__ oKl,
    __half* __restrict__ oVth)
{
    extern __shared__ __half smem[];
    const int tid = threadIdx.x;
    const int wid = tid >> 5, lane = tid & 31;
    const int g = lane >> 2, tig = lane & 3;
    const int warpRow = (wid >> 1) * 32;
    const int warpCol = (wid & 1) * 64;
    const int rowBase = blockIdx.y * 128;
    const int colBase = blockIdx.x * 128;
    const int region = (MODE == 2) ? (colBase >> 10) : 0;   // 0:Q 1:K 2:V
    const bool need3 = (MODE == 2) && (region < 2);         // 3rd MMA + Bl tiles

    const __half* gA0 = Ah_ + (size_t)rowBase * GK;
    const __half* gA1 = Al_ + (size_t)rowBase * GK;
    const __half* gB0 = Bh_ + (size_t)colBase * GK;
    const __half* gB1 = Bl_ + (size_t)colBase * GK;

    float acc[2][8][4];
    #pragma unroll
    for (int mt = 0; mt < 2; mt++)
        #pragma unroll
        for (int nt = 0; nt < 8; nt++)
            #pragma unroll
            for (int j = 0; j < 4; j++) acc[mt][nt][j] = 0.f;

    const int lr = tid >> 1, lh = tid & 1;
    const uint32_t sbase = smem_u32(smem);
    const size_t gbase = (size_t)lr * GK + lh * 16;
    const uint32_t sb0 = sbase + (lr * AS2 + lh * 16) * 2;

    const int frow = (lane & 7) + ((lane >> 3) & 1) * 8;
    const int fcol = (lane >> 4) * 8;

    const int NIT = GK / BK2;  // 32

    {
        #pragma unroll
        for (int c = 0; c < 2; c++) {
            cp16(sb0 + c * 16 + 0 * MAT_E * 2, gA0 + gbase + c * 8);
            cp16(sb0 + c * 16 + 1 * MAT_E * 2, gA1 + gbase + c * 8);
            cp16(sb0 + c * 16 + 2 * MAT_E * 2, gB0 + gbase + c * 8);
            if (need3) cp16(sb0 + c * 16 + 3 * MAT_E * 2, gB1 + gbase + c * 8);
        }
        asm volatile("cp.async.commit_group;" ::: "memory");
    }

    for (int it = 0; it < NIT; it++) {
        if (it + 1 < NIT) {
            const int k0 = (it + 1) * BK2;
            const uint32_t sb = sb0 + ((it + 1) & 1) * STG_E * 2;
            #pragma unroll
            for (int c = 0; c < 2; c++) {
                cp16(sb + c * 16 + 0 * MAT_E * 2, gA0 + gbase + k0 + c * 8);
                cp16(sb + c * 16 + 1 * MAT_E * 2, gA1 + gbase + k0 + c * 8);
                cp16(sb + c * 16 + 2 * MAT_E * 2, gB0 + gbase + k0 + c * 8);
                if (need3) cp16(sb + c * 16 + 3 * MAT_E * 2, gB1 + gbase + k0 + c * 8);
            }
            asm volatile("cp.async.commit_group;" ::: "memory");
            asm volatile("cp.async.wait_group 1;" ::: "memory");
        } else {
            asm volatile("cp.async.wait_group 0;" ::: "memory");
        }
        __syncthreads();

        const uint32_t stg = sbase + (it & 1) * STG_E * 2;

        #pragma unroll
        for (int ks = 0; ks < 2; ks++) {
            const uint32_t cb = (uint32_t)(ks * 16 + fcol) * 2;
            uint32_t ah[2][4], al[2][4];
            #pragma unroll
            for (int mt = 0; mt < 2; mt++) {
                const uint32_t rb = (uint32_t)(warpRow + mt * 16 + frow) * (AS2 * 2);
                ldsm4(ah[mt], stg + 0 * MAT_E * 2 + rb + cb);
                ldsm4(al[mt], stg + 1 * MAT_E * 2 + rb + cb);
            }
            #pragma unroll
            for (int ntp = 0; ntp < 4; ntp++) {
                const uint32_t rb = (uint32_t)(warpCol + ntp * 16 + frow) * (AS2 * 2);
                uint32_t bh4[4], bl4[4];
                ldsm4(bh4, stg + 2 * MAT_E * 2 + rb + cb);
                if (need3) ldsm4(bl4, stg + 3 * MAT_E * 2 + rb + cb);
                #pragma unroll
                for (int s = 0; s < 2; s++) {
                    const int nt = ntp * 2 + s;
                    #pragma unroll
                    for (int mt = 0; mt < 2; mt++) {
                        mma_f16(acc[mt][nt], ah[mt], bh4[s], bh4[2 + s]);
                        mma_f16(acc[mt][nt], al[mt], bh4[s], bh4[2 + s]);
                        if (need3)
                            mma_f16(acc[mt][nt], ah[mt], bl4[s], bl4[2 + s]);
                    }
                }
            }
        }
        __syncthreads();
    }

    // ---------------- epilogue ----------------
    if (MODE == 2 && region == 2) {
        // V: transpose through smem, write Vt[(b*16+h)*64+d][seq] hi only
        __half* tH = smem;   // [128][VT_STR]
        #pragma unroll
        for (int mt = 0; mt < 2; mt++) {
            #pragma unroll
            for (int nt = 0; nt < 8; nt++) {
                const int cl = warpCol + nt * 8 + tig * 2;
                const int rl = warpRow + mt * 16 + g;
                #pragma unroll
                for (int j = 0; j < 4; j++) {
                    const int c = cl + (j & 1);
                    const int r = rl + (j >> 1) * 8;
                    tH[c * VT_STR + r] = __float2half_rn(acc[mt][nt][j]);
                }
            }
        }
        __syncthreads();
        const int dl = tid >> 1, hf = tid & 1;
        const int bq = rowBase / NSEQ;
        const int seq0 = rowBase & (NSEQ - 1);
        const int h0 = (colBase & 1023) >> 6;
        const size_t orow = ((size_t)(bq * NHEAD + h0) * HDIM + dl) * NSEQ + seq0 + hf * 64;
        const __half* sH = tH + dl * VT_STR + hf * 64;
        #pragma unroll
        for (int u = 0; u < 8; u++)
            *(uint4*)(oVth + orow + u * 8) = *(const uint4*)(sH + u * 8);
        return;
    }

    #pragma unroll
    for (int mt = 0; mt < 2; mt++) {
        #pragma unroll
        for (int nt = 0; nt < 8; nt++) {
            const int r0 = rowBase + warpRow + mt * 16 + g;
            if (MODE == 0) {
                const int col = colBase + warpCol + nt * 8 + tig * 2;
                float bx = bias ? bias[col] : 0.f;
                float by = bias ? bias[col + 1] : 0.f;
                float2 v0 = {acc[mt][nt][0] + bx, acc[mt][nt][1] + by};
                float2 v1 = {acc[mt][nt][2] + bx, acc[mt][nt][3] + by};
                *(float2*)(C + (size_t)r0 * D_IN + col) = v0;
                *(float2*)(C + (size_t)(r0 + 8) * D_IN + col) = v1;
            } else {
                const int col = (colBase & 1023) + warpCol + nt * 8 + tig * 2;
                __half* Ho = (region == 0) ? oQh : oKh;
                __half* Lo = (region == 0) ? oQl : oKl;
                float2 v0 = {acc[mt][nt][0], acc[mt][nt][1]};
                float2 v1 = {acc[mt][nt][2], acc[mt][nt][3]};
                __half2 h0 = __float22half2_rn(v0);
                __half2 h1 = __float22half2_rn(v1);
                __half2 l0 = __float22half2_rn(make_float2(
                    v0.x - __half2float(h0.x), v0.y - __half2float(h0.y)));
                __half2 l1 = __float22half2_rn(make_float2(
                    v1.x - __half2float(h1.x), v1.y - __half2float(h1.y)));
                *(uint32_t*)(Ho + (size_t)r0 * D_IN + col) = *(uint32_t*)&h0;
                *(uint32_t*)(Ho + (size_t)(r0 + 8) * D_IN + col) = *(uint32_t*)&h1;
                *(uint32_t*)(Lo + (size_t)r0 * D_IN + col) = *(uint32_t*)&l0;
                *(uint32_t*)(Lo + (size_t)(r0 + 8) * D_IN + col) = *(uint32_t*)&l1;
            }
        }
    }
}

// ---------------------------------------------------------------------------
// Tensor-core causal flash attention. QK: 3-MMA fp16 split; PV: 2-MMA
// (P hi/lo x Vh). cp.async double-buffered K/V tiles (3 tiles/stage).
// ---------------------------------------------------------------------------
#define KSTR 72
#define TILE_B2 (64 * KSTR * 2)          // 9216 bytes per tile
#define ASTAGE_B (3 * TILE_B2)           // 27648 bytes per stage
#define ATTN_SMEM2 (2 * ASTAGE_B)        // 55296 bytes
#define EXP_C 0.1803368801111204f        // log2(e)/8

__global__ __launch_bounds__(256) void attn_mma_kernel(
    const __half* __restrict__ Qh, const __half* __restrict__ Ql,
    const __half* __restrict__ Kh, const __half* __restrict__ Kl,
    const __half* __restrict__ Vth,
    __half* __restrict__ Ch, __half* __restrict__ Cl)
{
    extern __shared__ __half asmem[];
    const uint32_t sb = smem_u32(asmem);

    const int tid = threadIdx.x;
    const int wid = tid >> 5, lane = tid & 31;
    const int g = lane >> 2, tig = lane & 3;
    const int q0 = ((int)gridDim.x - 1 - (int)blockIdx.x) * 128;   // heavy first
    const int h = blockIdx.y, b = blockIdx.z;
    const int bh = b * NHEAD + h;
    const int rA = q0 + wid * 16 + g;
    const int rB = rA + 8;

    const size_t qrow = (size_t)(b * NSEQ + q0 + wid * 16) * D_IN + h * HDIM;
    uint32_t qh[4][4], ql[4][4];
    #pragma unroll
    for (int ks = 0; ks < 4; ks++) {
        const int col = ks * 16 + tig * 2;
        qh[ks][0] = *(const uint32_t*)(Qh + qrow + (size_t)g * D_IN + col);
        qh[ks][1] = *(const uint32_t*)(Qh + qrow + (size_t)(g + 8) * D_IN + col);
        qh[ks][2] = *(const uint32_t*)(Qh + qrow + (size_t)g * D_IN + col + 8);
        qh[ks][3] = *(const uint32_t*)(Qh + qrow + (size_t)(g + 8) * D_IN + col + 8);
        ql[ks][0] = *(const uint32_t*)(Ql + qrow + (size_t)g * D_IN + col);
        ql[ks][1] = *(const uint32_t*)(Ql + qrow + (size_t)(g + 8) * D_IN + col);
        ql[ks][2] = *(const uint32_t*)(Ql + qrow + (size_t)g * D_IN + col + 8);
        ql[ks][3] = *(const uint32_t*)(Ql + qrow + (size_t)(g + 8) * D_IN + col + 8);
    }

    float O[8][4];
    #pragma unroll
    for (int nt = 0; nt < 8; nt++)
        #pragma unroll
        for (int j = 0; j < 4; j++) O[nt][j] = 0.f;
    float la = 0.f, lb = 0.f;

    const int ktmax = (q0 + 127) >> 6;
    const int lr = tid >> 3, lc = (tid & 7) * 8;

    auto load_tile = [&](int kt, int stage) {
        const int k0 = kt * 64;
        const uint32_t st = sb + stage * ASTAGE_B;
        #pragma unroll
        for (int i = 0; i < 2; i++) {
            const int r = lr + i * 32;
            const size_t gk = (size_t)(b * NSEQ + k0 + r) * D_IN + h * HDIM + lc;
            const size_t gv = (size_t)(bh * HDIM + r) * NSEQ + k0 + lc;
            const uint32_t so = (uint32_t)(r * KSTR + lc) * 2;
            cp16(st + 0 * TILE_B2 + so, Kh + gk);
            cp16(st + 1 * TILE_B2 + so, Kl + gk);
            cp16(st + 2 * TILE_B2 + so, Vth + gv);
        }
        asm volatile("cp.async.commit_group;" ::: "memory");
    };

    load_tile(0, 0);

    for (int kt = 0; kt <= ktmax; kt++) {
        if (kt < ktmax) {
            load_tile(kt + 1, (kt + 1) & 1);
            asm volatile("cp.async.wait_group 1;" ::: "memory");
        } else {
            asm volatile("cp.async.wait_group 0;" ::: "memory");
        }
        __syncthreads();

        const int k0 = kt * 64;
        const __half* stg = asmem + (kt & 1) * (ASTAGE_B / 2);
        const __half* sKh = stg;
        const __half* sKl = stg + 64 * KSTR;
        const __half* sVh = stg + 2 * 64 * KSTR;

        if (k0 <= q0 + wid * 16 + 15) {
            float S[8][4];
            #pragma unroll
            for (int nt = 0; nt < 8; nt++)
                #pragma unroll
                for (int j = 0; j < 4; j++) S[nt][j] = 0.f;

            #pragma unroll
            for (int ks = 0; ks < 4; ks++) {
                const int koff = ks * 16 + tig * 2;
                #pragma unroll
                for (int nt = 0; nt < 8; nt++) {
                    const int n = nt * 8 + g;
                    uint32_t b0h = *(const uint32_t*)(sKh + n * KSTR + koff);
                    uint32_t b1h = *(const uint32_t*)(sKh + n * KSTR + koff + 8);
                    uint32_t b0l = *(const uint32_t*)(sKl + n * KSTR + koff);
                    uint32_t b1l = *(const uint32_t*)(sKl + n * KSTR + koff + 8);
                    mma_f16(S[nt], qh[ks], b0h, b1h);
                    mma_f16(S[nt], qh[ks], b0l, b1l);
                    mma_f16(S[nt], ql[ks], b0h, b1h);
                }
            }

            uint32_t ph[4][4], pl[4][4];
            #pragma unroll
            for (int nt = 0; nt < 8; nt++) {
                const int c0 = k0 + nt * 8 + tig * 2;
                const int c1 = c0 + 1;
                float p0 = (c0 <= rA) ? fexp2(S[nt][0] * EXP_C) : 0.f;
                float p1 = (c1 <= rA) ? fexp2(S[nt][1] * EXP_C) : 0.f;
                float p2 = (c0 <= rB) ? fexp2(S[nt][2] * EXP_C) : 0.f;
                float p3 = (c1 <= rB) ? fexp2(S[nt][3] * EXP_C) : 0.f;
                la += p0 + p1;
                lb += p2 + p3;
                __half2 h01 = __float22half2_rn(make_float2(p0, p1));
                __half2 h23 = __float22half2_rn(make_float2(p2, p3));
                __half2 l01 = __float22half2_rn(make_float2(
                    p0 - __half2float(h01.x), p1 - __half2float(h01.y)));
                __half2 l23 = __float22half2_rn(make_float2(
                    p2 - __half2float(h23.x), p3 - __half2float(h23.y)));
                const int ks = nt >> 1, half = (nt & 1) * 2;
                ph[ks][half + 0] = *(uint32_t*)&h01;
                ph[ks][half + 1] = *(uint32_t*)&h23;
                pl[ks][half + 0] = *(uint32_t*)&l01;
                pl[ks][half + 1] = *(uint32_t*)&l23;
            }

            #pragma unroll
            for (int ks = 0; ks < 4; ks++) {
                const int koff = ks * 16 + tig * 2;
                #pragma unroll
                for (int nt = 0; nt < 8; nt++) {
                    const int n = nt * 8 + g;
                    uint32_t b0h = *(const uint32_t*)(sVh + n * KSTR + koff);
                    uint32_t b1h = *(const uint32_t*)(sVh + n * KSTR + koff + 8);
                    mma_f16(O[nt], ph[ks], b0h, b1h);
                    mma_f16(O[nt], pl[ks], b0h, b1h);
                }
            }
        }
        __syncthreads();
    }

    la += __shfl_xor_sync(0xFFFFFFFF, la, 1);
    la += __shfl_xor_sync(0xFFFFFFFF, la, 2);
    lb += __shfl_xor_sync(0xFFFFFFFF, lb, 1);
    lb += __shfl_xor_sync(0xFFFFFFFF, lb, 2);
    const float ia = 1.f / la, ib = 1.f / lb;

    #pragma unroll
    for (int nt = 0; nt < 8; nt++) {
        const int col = h * HDIM + nt * 8 + tig * 2;
        float2 vA = {O[nt][0] * ia, O[nt][1] * ia};
        float2 vB = {O[nt][2] * ib, O[nt][3] * ib};
        __half2 hA = __float22half2_rn(vA);
        __half2 hB = __float22half2_rn(vB);
        __half2 lA = __float22half2_rn(make_float2(
            vA.x - __half2float(hA.x), vA.y - __half2float(hA.y)));
        __half2 lB = __float22half2_rn(make_float2(
            vB.x - __half2float(hB.x), vB.y - __half2float(hB.y)));
        *(uint32_t*)(Ch + (size_t)(b * NSEQ + rA) * D_IN + col) = *(uint32_t*)&hA;
        *(uint32_t*)(Ch + (size_t)(b * NSEQ + rB) * D_IN + col) = *(uint32_t*)&hB;
        *(uint32_t*)(Cl + (size_t)(b * NSEQ + rA) * D_IN + col) = *(uint32_t*)&lA;
        *(uint32_t*)(Cl + (size_t)(b * NSEQ + rB) * D_IN + col) = *(uint32_t*)&lB;
    }
}

// ---------------------------------------------------------------------------
extern "C" void kernel_launch(void* const* d_in, const int* in_sizes, int n_in,
                              void* d_out, int out_size)
{
    const float* X  = (const float*)d_in[0];
    const float* Wq = (const float*)d_in[1];
    const float* Wk = (const float*)d_in[2];
    const float* Wv = (const float*)d_in[3];
    const float* Wo = (const float*)d_in[4];
    const float* bo = (const float*)d_in[5];
    float* out = (float*)d_out;

    __half *pXh, *pXl, *pCh, *pCl, *pWth, *pWtl;
    __half *pQh, *pQl, *pKh, *pKl, *pVth;
    cudaGetSymbolAddress((void**)&pXh, g_Xh);
    cudaGetSymbolAddress((void**)&pXl, g_Xl);
    cudaGetSymbolAddress((void**)&pCh, g_Ch);
    cudaGetSymbolAddress((void**)&pCl, g_Cl);
    cudaGetSymbolAddress((void**)&pWth, g_Wth);
    cudaGetSymbolAddress((void**)&pWtl, g_Wtl);
    cudaGetSymbolAddress((void**)&pQh, g_Qh);
    cudaGetSymbolAddress((void**)&pQl, g_Ql);
    cudaGetSymbolAddress((void**)&pKh, g_Kh);
    cudaGetSymbolAddress((void**)&pKl, g_Kl);
    cudaGetSymbolAddress((void**)&pVth, g_Vth);

    static bool attrs_set = false;
    if (!attrs_set) {
        cudaFuncSetAttribute(gemm_ld_kernel<0>,
                             cudaFuncAttributeMaxDynamicSharedMemorySize, GSMEM);
        cudaFuncSetAttribute(gemm_ld_kernel<2>,
                             cudaFuncAttributeMaxDynamicSharedMemorySize, GSMEM);
        cudaFuncSetAttribute(attn_mma_kernel,
                             cudaFuncAttributeMaxDynamicSharedMemorySize, ATTN_SMEM2);
        attrs_set = true;
    }

    const int splitBlocks = (MTOT * D_IN) / (256 * 4);
    const dim3 trGrid(D_IN / 32, D_IN / 32), trBlk(32, 8);

    split_kernel<<<splitBlocks, 256>>>(X, pXh, pXl);

    transpose_split_kernel<<<trGrid, trBlk>>>(Wq, pWth, pWtl, 0);
    transpose_split_kernel<<<trGrid, trBlk>>>(Wk, pWth, pWtl, 1024);
    transpose_split_kernel<<<trGrid, trBlk>>>(Wv, pWth, pWtl, 2048);

    gemm_ld_kernel<2><<<dim3(NQKV / 128, MTOT / 128), 256, GSMEM>>>(
        pXh, pXl, pWth, pWtl, nullptr, nullptr,
        pQh, pQl, pKh, pKl, pVth);

    attn_mma_kernel<<<dim3(NSEQ / 128, NHEAD, BATCH), 256, ATTN_SMEM2>>>(
        pQh, pQl, pKh, pKl, pVth, pCh, pCl);

    transpose_split_kernel<<<trGrid, trBlk>>>(Wo, pWth, pWtl, 0);
    gemm_ld_kernel<0><<<dim3(D_IN / 128, MTOT / 128), 256, GSMEM>>>(
        pCh, pCl, pWth, pWtl, bo, out,
        nullptr, nullptr, nullptr, nullptr, nullptr);
}

// round 10
// speedup vs baseline: 1.5637x; 1.5637x over previous
#include <cuda_runtime.h>
#include <cuda_fp16.h>
#include <cstdint>

// Problem constants
#define D_IN   1024
#define NSEQ   2048
#define BATCH  4
#define NHEAD  16
#define HDIM   64
#define MTOT   (BATCH*NSEQ)   // 8192
#define GK     1024

// ---------------------------------------------------------------------------
// Scratch (no cudaMalloc allowed)
// ---------------------------------------------------------------------------
__device__ __half g_Xh[(size_t)MTOT * D_IN];
__device__ __half g_Xl[(size_t)MTOT * D_IN];
__device__ __half g_Ch[(size_t)MTOT * D_IN];
__device__ __half g_Cl[(size_t)MTOT * D_IN];
__device__ __half g_Wth[(size_t)3 * D_IN * D_IN];   // Wq|Wk|Wv transposed (Wo reuses)
__device__ __half g_Wtl[(size_t)3 * D_IN * D_IN];
__device__ __half g_Qh[(size_t)MTOT * D_IN];
__device__ __half g_Ql[(size_t)MTOT * D_IN];
__device__ __half g_Kh[(size_t)MTOT * D_IN];
__device__ __half g_Kl[(size_t)MTOT * D_IN];
__device__ __half g_Vth[(size_t)BATCH * NHEAD * HDIM * NSEQ];   // hi only

__device__ __forceinline__ float fexp2(float x) {
    float r;
    asm("ex2.approx.f32 %0, %1;" : "=f"(r) : "f"(x));
    return r;
}
__device__ __forceinline__ uint32_t smem_u32(const void* p) {
    uint32_t a;
    asm("{ .reg .u64 t; cvta.to.shared.u64 t, %1; cvt.u32.u64 %0, t; }" : "=r"(a) : "l"(p));
    return a;
}
__device__ __forceinline__ void cp16(uint32_t saddr, const void* gptr) {
    asm volatile("cp.async.cg.shared.global [%0], [%1], 16;" :: "r"(saddr), "l"(gptr));
}
__device__ __forceinline__ void ldsm4(uint32_t* r, uint32_t saddr) {
    asm volatile("ldmatrix.sync.aligned.m8n8.x4.shared.b16 {%0,%1,%2,%3}, [%4];"
        : "=r"(r[0]), "=r"(r[1]), "=r"(r[2]), "=r"(r[3]) : "r"(saddr));
}
__device__ __forceinline__ void mma_f16(float* c, const uint32_t* a,
                                        uint32_t b0, uint32_t b1)
{
    asm volatile(
        "mma.sync.aligned.m16n8k16.row.col.f32.f16.f16.f32 "
        "{%0,%1,%2,%3}, {%4,%5,%6,%7}, {%8,%9}, {%0,%1,%2,%3};"
        : "+f"(c[0]), "+f"(c[1]), "+f"(c[2]), "+f"(c[3])
        : "r"(a[0]), "r"(a[1]), "r"(a[2]), "r"(a[3]), "r"(b0), "r"(b1));
}

// ---------------------------------------------------------------------------
// Split fp32 -> fp16 hi + lo (X only)
// ---------------------------------------------------------------------------
__global__ __launch_bounds__(256) void split_kernel(
    const float* __restrict__ x, __half* __restrict__ hi,
    __half* __restrict__ lo)
{
    size_t i = (size_t)blockIdx.x * 256 + threadIdx.x;
    float4 v = ((const float4*)x)[i];
    __half h0 = __float2half_rn(v.x), h1 = __float2half_rn(v.y);
    __half h2 = __float2half_rn(v.z), h3 = __float2half_rn(v.w);
    __half l0 = __float2half_rn(v.x - __half2float(h0));
    __half l1 = __float2half_rn(v.y - __half2float(h1));
    __half l2 = __float2half_rn(v.z - __half2float(h2));
    __half l3 = __float2half_rn(v.w - __half2float(h3));
    __half2 hv0{h0, h1}, hv1{h2, h3}, lv0{l0, l1}, lv1{l2, l3};
    ((__half2*)hi)[i * 2 + 0] = hv0;
    ((__half2*)hi)[i * 2 + 1] = hv1;
    ((__half2*)lo)[i * 2 + 0] = lv0;
    ((__half2*)lo)[i * 2 + 1] = lv1;
}

// ---------------------------------------------------------------------------
// Transpose + split weights: W[K,1024] fp32 -> Wt[rowOff+N][K] fp16 hi/lo
// ---------------------------------------------------------------------------
__global__ __launch_bounds__(256) void transpose_split_kernel(
    const float* __restrict__ W, __half* __restrict__ Th,
    __half* __restrict__ Tl, int rowOff)
{
    __shared__ float t[32][33];
    int x0 = blockIdx.x * 32, y0 = blockIdx.y * 32;
    int tx = threadIdx.x, ty = threadIdx.y;  // (32, 8)
    #pragma unroll
    for (int j = 0; j < 32; j += 8)
        t[ty + j][tx] = W[(size_t)(y0 + ty + j) * D_IN + x0 + tx];
    __syncthreads();
    #pragma unroll
    for (int j = 0; j < 32; j += 8) {
        float v = t[tx][ty + j];
        __half h = __float2half_rn(v);
        size_t o = (size_t)(rowOff + x0 + ty + j) * GK + y0 + tx;
        Th[o] = h;
        Tl[o] = __float2half_rn(v - __half2float(h));
    }
}

// ---------------------------------------------------------------------------
// Pipelined split-fp16 GEMM, branch-free per instantiation.
// NMMA: 3 = AhBh+AlBh+AhBl,  2 = AhBh+AlBh (no Bl tiles at all).
// EPI:  0 = fp32 + bias,  1 = split-fp16 Q/K routing,  2 = Vt-hi transpose.
// ---------------------------------------------------------------------------
#define BK2 32
#define AS2 40
#define MAT_E (128 * AS2)
#define STG_E (4 * MAT_E)          // fixed stage stride (Bl slot unused when NMMA==2)
#define GSMEM (2 * STG_E * 2)      // 81920 bytes
#define VT_STR 136

template<int NMMA, int EPI>
__global__ __launch_bounds__(256, 2) void gemm_ld_kernel(
    const __half* __restrict__ Ah_, const __half* __restrict__ Al_,
    const __half* __restrict__ Bh_, const __half* __restrict__ Bl_,
    const float* __restrict__ bias, float* __restrict__ C,
    __half* __restrict__ oQh, __half* __restrict__ oQl,
    __half* __restrict__ oKh, __half* __restrict__ oKl,
    __half* __restrict__ oVth)
{
    extern __shared__ __half smem[];
    const int tid = threadIdx.x;
    const int wid = tid >> 5, lane = tid & 31;
    const int g = lane >> 2, tig = lane & 3;
    const int warpRow = (wid >> 1) * 32;
    const int warpCol = (wid & 1) * 64;
    const int rowBase = blockIdx.y * 128;
    const int colBase = blockIdx.x * 128;

    const __half* gA0 = Ah_ + (size_t)rowBase * GK;
    const __half* gA1 = Al_ + (size_t)rowBase * GK;
    const __half* gB0 = Bh_ + (size_t)colBase * GK;
    const __half* gB1 = Bl_ + (size_t)colBase * GK;

    float acc[2][8][4];
    #pragma unroll
    for (int mt = 0; mt < 2; mt++)
        #pragma unroll
        for (int nt = 0; nt < 8; nt++)
            #pragma unroll
            for (int j = 0; j < 4; j++) acc[mt][nt][j] = 0.f;

    const int lr = tid >> 1, lh = tid & 1;
    const uint32_t sbase = smem_u32(smem);
    const size_t gbase = (size_t)lr * GK + lh * 16;
    const uint32_t sb0 = sbase + (lr * AS2 + lh * 16) * 2;

    const int frow = (lane & 7) + ((lane >> 3) & 1) * 8;
    const int fcol = (lane >> 4) * 8;

    const int NIT = GK / BK2;  // 32

    {
        #pragma unroll
        for (int c = 0; c < 2; c++) {
            cp16(sb0 + c * 16 + 0 * MAT_E * 2, gA0 + gbase + c * 8);
            cp16(sb0 + c * 16 + 1 * MAT_E * 2, gA1 + gbase + c * 8);
            cp16(sb0 + c * 16 + 2 * MAT_E * 2, gB0 + gbase + c * 8);
            if (NMMA == 3) cp16(sb0 + c * 16 + 3 * MAT_E * 2, gB1 + gbase + c * 8);
        }
        asm volatile("cp.async.commit_group;" ::: "memory");
    }

    for (int it = 0; it < NIT; it++) {
        if (it + 1 < NIT) {
            const int k0 = (it + 1) * BK2;
            const uint32_t sb = sb0 + ((it + 1) & 1) * STG_E * 2;
            #pragma unroll
            for (int c = 0; c < 2; c++) {
                cp16(sb + c * 16 + 0 * MAT_E * 2, gA0 + gbase + k0 + c * 8);
                cp16(sb + c * 16 + 1 * MAT_E * 2, gA1 + gbase + k0 + c * 8);
                cp16(sb + c * 16 + 2 * MAT_E * 2, gB0 + gbase + k0 + c * 8);
                if (NMMA == 3) cp16(sb + c * 16 + 3 * MAT_E * 2, gB1 + gbase + k0 + c * 8);
            }
            asm volatile("cp.async.commit_group;" ::: "memory");
            asm volatile("cp.async.wait_group 1;" ::: "memory");
        } else {
            asm volatile("cp.async.wait_group 0;" ::: "memory");
        }
        __syncthreads();

        const uint32_t stg = sbase + (it & 1) * STG_E * 2;

        #pragma unroll
        for (int ks = 0; ks < 2; ks++) {
            const uint32_t cb = (uint32_t)(ks * 16 + fcol) * 2;
            uint32_t ah[2][4], al[2][4];
            #pragma unroll
            for (int mt = 0; mt < 2; mt++) {
                const uint32_t rb = (uint32_t)(warpRow + mt * 16 + frow) * (AS2 * 2);
                ldsm4(ah[mt], stg + 0 * MAT_E * 2 + rb + cb);
                ldsm4(al[mt], stg + 1 * MAT_E * 2 + rb + cb);
            }
            #pragma unroll
            for (int ntp = 0; ntp < 4; ntp++) {
                const uint32_t rb = (uint32_t)(warpCol + ntp * 16 + frow) * (AS2 * 2);
                uint32_t bh4[4];
                ldsm4(bh4, stg + 2 * MAT_E * 2 + rb + cb);
                if (NMMA == 3) {
                    uint32_t bl4[4];
                    ldsm4(bl4, stg + 3 * MAT_E * 2 + rb + cb);
                    #pragma unroll
                    for (int s = 0; s < 2; s++) {
                        const int nt = ntp * 2 + s;
                        #pragma unroll
                        for (int mt = 0; mt < 2; mt++) {
                            mma_f16(acc[mt][nt], ah[mt], bh4[s], bh4[2 + s]);
                            mma_f16(acc[mt][nt], al[mt], bh4[s], bh4[2 + s]);
                            mma_f16(acc[mt][nt], ah[mt], bl4[s], bl4[2 + s]);
                        }
                    }
                } else {
                    #pragma unroll
                    for (int s = 0; s < 2; s++) {
                        const int nt = ntp * 2 + s;
                        #pragma unroll
                        for (int mt = 0; mt < 2; mt++) {
                            mma_f16(acc[mt][nt], ah[mt], bh4[s], bh4[2 + s]);
                            mma_f16(acc[mt][nt], al[mt], bh4[s], bh4[2 + s]);
                        }
                    }
                }
            }
        }
        __syncthreads();
    }

    // ---------------- epilogue ----------------
    if (EPI == 2) {
        // Vt-hi transpose: write Vt[(b*16+h)*64+d][seq]
        __half* tH = smem;   // [128][VT_STR]
        #pragma unroll
        for (int mt = 0; mt < 2; mt++) {
            #pragma unroll
            for (int nt = 0; nt < 8; nt++) {
                const int cl = warpCol + nt * 8 + tig * 2;
                const int rl = warpRow + mt * 16 + g;
                #pragma unroll
                for (int j = 0; j < 4; j++) {
                    const int c = cl + (j & 1);
                    const int r = rl + (j >> 1) * 8;
                    tH[c * VT_STR + r] = __float2half_rn(acc[mt][nt][j]);
                }
            }
        }
        __syncthreads();
        const int dl = tid >> 1, hf = tid & 1;
        const int bq = rowBase / NSEQ;
        const int seq0 = rowBase & (NSEQ - 1);
        const int h0 = colBase >> 6;    // head = V-col/64 (colBase is V-local here)
        const size_t orow = ((size_t)(bq * NHEAD + h0) * HDIM + dl) * NSEQ + seq0 + hf * 64;
        const __half* sH = tH + dl * VT_STR + hf * 64;
        #pragma unroll
        for (int u = 0; u < 8; u++)
            *(uint4*)(oVth + orow + u * 8) = *(const uint4*)(sH + u * 8);
        return;
    }

    #pragma unroll
    for (int mt = 0; mt < 2; mt++) {
        #pragma unroll
        for (int nt = 0; nt < 8; nt++) {
            const int r0 = rowBase + warpRow + mt * 16 + g;
            if (EPI == 0) {
                const int col = colBase + warpCol + nt * 8 + tig * 2;
                float bx = bias[col], by = bias[col + 1];
                float2 v0 = {acc[mt][nt][0] + bx, acc[mt][nt][1] + by};
                float2 v1 = {acc[mt][nt][2] + bx, acc[mt][nt][3] + by};
                *(float2*)(C + (size_t)r0 * D_IN + col) = v0;
                *(float2*)(C + (size_t)(r0 + 8) * D_IN + col) = v1;
            } else {
                const int region = colBase >> 10;                  // 0:Q 1:K
                const int col = (colBase & 1023) + warpCol + nt * 8 + tig * 2;
                __half* Ho = (region == 0) ? oQh : oKh;
                __half* Lo = (region == 0) ? oQl : oKl;
                float2 v0 = {acc[mt][nt][0], acc[mt][nt][1]};
                float2 v1 = {acc[mt][nt][2], acc[mt][nt][3]};
                __half2 h0 = __float22half2_rn(v0);
                __half2 h1 = __float22half2_rn(v1);
                __half2 l0 = __float22half2_rn(make_float2(
                    v0.x - __half2float(h0.x), v0.y - __half2float(h0.y)));
                __half2 l1 = __float22half2_rn(make_float2(
                    v1.x - __half2float(h1.x), v1.y - __half2float(h1.y)));
                *(uint32_t*)(Ho + (size_t)r0 * D_IN + col) = *(uint32_t*)&h0;
                *(uint32_t*)(Ho + (size_t)(r0 + 8) * D_IN + col) = *(uint32_t*)&h1;
                *(uint32_t*)(Lo + (size_t)r0 * D_IN + col) = *(uint32_t*)&l0;
                *(uint32_t*)(Lo + (size_t)(r0 + 8) * D_IN + col) = *(uint32_t*)&l1;
            }
        }
    }
}

// ---------------------------------------------------------------------------
// Tensor-core causal flash attention. QK: 3-MMA fp16 split; PV: 2-MMA.
// cp.async double-buffered tiles (Kh, Kl, Vh per stage). Heavy-first order.
// ---------------------------------------------------------------------------
#define KSTR 72
#define TILE_B2 (64 * KSTR * 2)
#define ASTAGE_B (3 * TILE_B2)
#define ATTN_SMEM2 (2 * ASTAGE_B)        // 55296 bytes
#define EXP_C 0.1803368801111204f        // log2(e)/8

__global__ __launch_bounds__(256) void attn_mma_kernel(
    const __half* __restrict__ Qh, const __half* __restrict__ Ql,
    const __half* __restrict__ Kh, const __half* __restrict__ Kl,
    const __half* __restrict__ Vth,
    __half* __restrict__ Ch, __half* __restrict__ Cl)
{
    extern __shared__ __half asmem[];
    const uint32_t sb = smem_u32(asmem);

    const int tid = threadIdx.x;
    const int wid = tid >> 5, lane = tid & 31;
    const int g = lane >> 2, tig = lane & 3;
    const int q0 = ((int)gridDim.x - 1 - (int)blockIdx.x) * 128;
    const int h = blockIdx.y, b = blockIdx.z;
    const int bh = b * NHEAD + h;
    const int rA = q0 + wid * 16 + g;
    const int rB = rA + 8;

    const size_t qrow = (size_t)(b * NSEQ + q0 + wid * 16) * D_IN + h * HDIM;
    uint32_t qh[4][4], ql[4][4];
    #pragma unroll
    for (int ks = 0; ks < 4; ks++) {
        const int col = ks * 16 + tig * 2;
        qh[ks][0] = *(const uint32_t*)(Qh + qrow + (size_t)g * D_IN + col);
        qh[ks][1] = *(const uint32_t*)(Qh + qrow + (size_t)(g + 8) * D_IN + col);
        qh[ks][2] = *(const uint32_t*)(Qh + qrow + (size_t)g * D_IN + col + 8);
        qh[ks][3] = *(const uint32_t*)(Qh + qrow + (size_t)(g + 8) * D_IN + col + 8);
        ql[ks][0] = *(const uint32_t*)(Ql + qrow + (size_t)g * D_IN + col);
        ql[ks][1] = *(const uint32_t*)(Ql + qrow + (size_t)(g + 8) * D_IN + col);
        ql[ks][2] = *(const uint32_t*)(Ql + qrow + (size_t)g * D_IN + col + 8);
        ql[ks][3] = *(const uint32_t*)(Ql + qrow + (size_t)(g + 8) * D_IN + col + 8);
    }

    float O[8][4];
    #pragma unroll
    for (int nt = 0; nt < 8; nt++)
        #pragma unroll
        for (int j = 0; j < 4; j++) O[nt][j] = 0.f;
    float la = 0.f, lb = 0.f;

    const int ktmax = (q0 + 127) >> 6;
    const int lr = tid >> 3, lc = (tid & 7) * 8;

    auto load_tile = [&](int kt, int stage) {
        const int k0 = kt * 64;
        const uint32_t st = sb + stage * ASTAGE_B;
        #pragma unroll
        for (int i = 0; i < 2; i++) {
            const int r = lr + i * 32;
            const size_t gk = (size_t)(b * NSEQ + k0 + r) * D_IN + h * HDIM + lc;
            const size_t gv = (size_t)(bh * HDIM + r) * NSEQ + k0 + lc;
            const uint32_t so = (uint32_t)(r * KSTR + lc) * 2;
            cp16(st + 0 * TILE_B2 + so, Kh + gk);
            cp16(st + 1 * TILE_B2 + so, Kl + gk);
            cp16(st + 2 * TILE_B2 + so, Vth + gv);
        }
        asm volatile("cp.async.commit_group;" ::: "memory");
    };

    load_tile(0, 0);

    for (int kt = 0; kt <= ktmax; kt++) {
        if (kt < ktmax) {
            load_tile(kt + 1, (kt + 1) & 1);
            asm volatile("cp.async.wait_group 1;" ::: "memory");
        } else {
            asm volatile("cp.async.wait_group 0;" ::: "memory");
        }
        __syncthreads();

        const int k0 = kt * 64;
        const __half* stg = asmem + (kt & 1) * (ASTAGE_B / 2);
        const __half* sKh = stg;
        const __half* sKl = stg + 64 * KSTR;
        const __half* sVh = stg + 2 * 64 * KSTR;

        if (k0 <= q0 + wid * 16 + 15) {
            float S[8][4];
            #pragma unroll
            for (int nt = 0; nt < 8; nt++)
                #pragma unroll
                for (int j = 0; j < 4; j++) S[nt][j] = 0.f;

            #pragma unroll
            for (int ks = 0; ks < 4; ks++) {
                const int koff = ks * 16 + tig * 2;
                #pragma unroll
                for (int nt = 0; nt < 8; nt++) {
                    const int n = nt * 8 + g;
                    uint32_t b0h = *(const uint32_t*)(sKh + n * KSTR + koff);
                    uint32_t b1h = *(const uint32_t*)(sKh + n * KSTR + koff + 8);
                    uint32_t b0l = *(const uint32_t*)(sKl + n * KSTR + koff);
                    uint32_t b1l = *(const uint32_t*)(sKl + n * KSTR + koff + 8);
                    mma_f16(S[nt], qh[ks], b0h, b1h);
                    mma_f16(S[nt], qh[ks], b0l, b1l);
                    mma_f16(S[nt], ql[ks], b0h, b1h);
                }
            }

            uint32_t ph[4][4], pl[4][4];
            #pragma unroll
            for (int nt = 0; nt < 8; nt++) {
                const int c0 = k0 + nt * 8 + tig * 2;
                const int c1 = c0 + 1;
                float p0 = (c0 <= rA) ? fexp2(S[nt][0] * EXP_C) : 0.f;
                float p1 = (c1 <= rA) ? fexp2(S[nt][1] * EXP_C) : 0.f;
                float p2 = (c0 <= rB) ? fexp2(S[nt][2] * EXP_C) : 0.f;
                float p3 = (c1 <= rB) ? fexp2(S[nt][3] * EXP_C) : 0.f;
                la += p0 + p1;
                lb += p2 + p3;
                __half2 h01 = __float22half2_rn(make_float2(p0, p1));
                __half2 h23 = __float22half2_rn(make_float2(p2, p3));
                __half2 l01 = __float22half2_rn(make_float2(
                    p0 - __half2float(h01.x), p1 - __half2float(h01.y)));
                __half2 l23 = __float22half2_rn(make_float2(
                    p2 - __half2float(h23.x), p3 - __half2float(h23.y)));
                const int ks = nt >> 1, half = (nt & 1) * 2;
                ph[ks][half + 0] = *(uint32_t*)&h01;
                ph[ks][half + 1] = *(uint32_t*)&h23;
                pl[ks][half + 0] = *(uint32_t*)&l01;
                pl[ks][half + 1] = *(uint32_t*)&l23;
            }

            #pragma unroll
            for (int ks = 0; ks < 4; ks++) {
                const int koff = ks * 16 + tig * 2;
                #pragma unroll
                for (int nt = 0; nt < 8; nt++) {
                    const int n = nt * 8 + g;
                    uint32_t b0h = *(const uint32_t*)(sVh + n * KSTR + koff);
                    uint32_t b1h = *(const uint32_t*)(sVh + n * KSTR + koff + 8);
                    mma_f16(O[nt], ph[ks], b0h, b1h);
                    mma_f16(O[nt], pl[ks], b0h, b1h);
                }
            }
        }
        __syncthreads();
    }

    la += __shfl_xor_sync(0xFFFFFFFF, la, 1);
    la += __shfl_xor_sync(0xFFFFFFFF, la, 2);
    lb += __shfl_xor_sync(0xFFFFFFFF, lb, 1);
    lb += __shfl_xor_sync(0xFFFFFFFF, lb, 2);
    const float ia = 1.f / la, ib = 1.f / lb;

    #pragma unroll
    for (int nt = 0; nt < 8; nt++) {
        const int col = h * HDIM + nt * 8 + tig * 2;
        float2 vA = {O[nt][0] * ia, O[nt][1] * ia};
        float2 vB = {O[nt][2] * ib, O[nt][3] * ib};
        __half2 hA = __float22half2_rn(vA);
        __half2 hB = __float22half2_rn(vB);
        __half2 lA = __float22half2_rn(make_float2(
            vA.x - __half2float(hA.x), vA.y - __half2float(hA.y)));
        __half2 lB = __float22half2_rn(make_float2(
            vB.x - __half2float(hB.x), vB.y - __half2float(hB.y)));
        *(uint32_t*)(Ch + (size_t)(b * NSEQ + rA) * D_IN + col) = *(uint32_t*)&hA;
        *(uint32_t*)(Ch + (size_t)(b * NSEQ + rB) * D_IN + col) = *(uint32_t*)&hB;
        *(uint32_t*)(Cl + (size_t)(b * NSEQ + rA) * D_IN + col) = *(uint32_t*)&lA;
        *(uint32_t*)(Cl + (size_t)(b * NSEQ + rB) * D_IN + col) = *(uint32_t*)&lB;
    }
}

// ---------------------------------------------------------------------------
extern "C" void kernel_launch(void* const* d_in, const int* in_sizes, int n_in,
                              void* d_out, int out_size)
{
    const float* X  = (const float*)d_in[0];
    const float* Wq = (const float*)d_in[1];
    const float* Wk = (const float*)d_in[2];
    const float* Wv = (const float*)d_in[3];
    const float* Wo = (const float*)d_in[4];
    const float* bo = (const float*)d_in[5];
    float* out = (float*)d_out;

    __half *pXh, *pXl, *pCh, *pCl, *pWth, *pWtl;
    __half *pQh, *pQl, *pKh, *pKl, *pVth;
    cudaGetSymbolAddress((void**)&pXh, g_Xh);
    cudaGetSymbolAddress((void**)&pXl, g_Xl);
    cudaGetSymbolAddress((void**)&pCh, g_Ch);
    cudaGetSymbolAddress((void**)&pCl, g_Cl);
    cudaGetSymbolAddress((void**)&pWth, g_Wth);
    cudaGetSymbolAddress((void**)&pWtl, g_Wtl);
    cudaGetSymbolAddress((void**)&pQh, g_Qh);
    cudaGetSymbolAddress((void**)&pQl, g_Ql);
    cudaGetSymbolAddress((void**)&pKh, g_Kh);
    cudaGetSymbolAddress((void**)&pKl, g_Kl);
    cudaGetSymbolAddress((void**)&pVth, g_Vth);

    static bool attrs_set = false;
    if (!attrs_set) {
        cudaFuncSetAttribute((const void*)gemm_ld_kernel<3, 1>,
                             cudaFuncAttributeMaxDynamicSharedMemorySize, GSMEM);
        cudaFuncSetAttribute((const void*)gemm_ld_kernel<2, 2>,
                             cudaFuncAttributeMaxDynamicSharedMemorySize, GSMEM);
        cudaFuncSetAttribute((const void*)gemm_ld_kernel<2, 0>,
                             cudaFuncAttributeMaxDynamicSharedMemorySize, GSMEM);
        cudaFuncSetAttribute(attn_mma_kernel,
                             cudaFuncAttributeMaxDynamicSharedMemorySize, ATTN_SMEM2);
        attrs_set = true;
    }

    const int splitBlocks = (MTOT * D_IN) / (256 * 4);
    const dim3 trGrid(D_IN / 32, D_IN / 32), trBlk(32, 8);

    split_kernel<<<splitBlocks, 256>>>(X, pXh, pXl);

    transpose_split_kernel<<<trGrid, trBlk>>>(Wq, pWth, pWtl, 0);
    transpose_split_kernel<<<trGrid, trBlk>>>(Wk, pWth, pWtl, 1024);
    transpose_split_kernel<<<trGrid, trBlk>>>(Wv, pWth, pWtl, 2048);

    // QK projections: 3-MMA, columns 0..2047 of fused weight buffer
    gemm_ld_kernel<3, 1><<<dim3(16, MTOT / 128), 256, GSMEM>>>(
        pXh, pXl, pWth, pWtl, nullptr, nullptr,
        pQh, pQl, pKh, pKl, nullptr);
    // V projection: 2-MMA, columns 2048..3071, Vt-hi transpose epilogue
    gemm_ld_kernel<2, 2><<<dim3(8, MTOT / 128), 256, GSMEM>>>(
        pXh, pXl, pWth + (size_t)2048 * GK, pWtl, nullptr, nullptr,
        nullptr, nullptr, nullptr, nullptr, pVth);

    attn_mma_kernel<<<dim3(NSEQ / 128, NHEAD, BATCH), 256, ATTN_SMEM2>>>(
        pQh, pQl, pKh, pKl, pVth, pCh, pCl);

    transpose_split_kernel<<<trGrid, trBlk>>>(Wo, pWth, pWtl, 0);
    gemm_ld_kernel<2, 0><<<dim3(8, MTOT / 128), 256, GSMEM>>>(
        pCh, pCl, pWth, pWtl, bo, out,
        nullptr, nullptr, nullptr, nullptr, nullptr);
}

// round 11
// speedup vs baseline: 1.7640x; 1.1281x over previous
#include <cuda_runtime.h>
#include <cuda_fp16.h>
#include <cstdint>

// Problem constants
#define D_IN   1024
#define NSEQ   2048
#define BATCH  4
#define NHEAD  16
#define HDIM   64
#define MTOT   (BATCH*NSEQ)   // 8192
#define GK     1024

// ---------------------------------------------------------------------------
// Scratch (no cudaMalloc allowed)
// ---------------------------------------------------------------------------
__device__ __half g_Xh[(size_t)MTOT * D_IN];
__device__ __half g_Xl[(size_t)MTOT * D_IN];
__device__ __half g_Ch[(size_t)MTOT * D_IN];            // ctx hi only
__device__ __half g_Wth[(size_t)3 * D_IN * D_IN];       // Wq|Wk|Wv transposed (Wo reuses)
__device__ __half g_Wtl[(size_t)3 * D_IN * D_IN];
__device__ __half g_Qh[(size_t)MTOT * D_IN];
__device__ __half g_Ql[(size_t)MTOT * D_IN];
__device__ __half g_Kh[(size_t)MTOT * D_IN];
__device__ __half g_Kl[(size_t)MTOT * D_IN];
__device__ __half g_Vth[(size_t)BATCH * NHEAD * HDIM * NSEQ];   // hi only

__device__ __forceinline__ float fexp2(float x) {
    float r;
    asm("ex2.approx.f32 %0, %1;" : "=f"(r) : "f"(x));
    return r;
}
__device__ __forceinline__ uint32_t smem_u32(const void* p) {
    uint32_t a;
    asm("{ .reg .u64 t; cvta.to.shared.u64 t, %1; cvt.u32.u64 %0, t; }" : "=r"(a) : "l"(p));
    return a;
}
__device__ __forceinline__ void cp16(uint32_t saddr, const void* gptr) {
    asm volatile("cp.async.cg.shared.global [%0], [%1], 16;" :: "r"(saddr), "l"(gptr));
}
__device__ __forceinline__ void ldsm4(uint32_t* r, uint32_t saddr) {
    asm volatile("ldmatrix.sync.aligned.m8n8.x4.shared.b16 {%0,%1,%2,%3}, [%4];"
        : "=r"(r[0]), "=r"(r[1]), "=r"(r[2]), "=r"(r[3]) : "r"(saddr));
}
__device__ __forceinline__ void mma_f16(float* c, const uint32_t* a,
                                        uint32_t b0, uint32_t b1)
{
    asm volatile(
        "mma.sync.aligned.m16n8k16.row.col.f32.f16.f16.f32 "
        "{%0,%1,%2,%3}, {%4,%5,%6,%7}, {%8,%9}, {%0,%1,%2,%3};"
        : "+f"(c[0]), "+f"(c[1]), "+f"(c[2]), "+f"(c[3])
        : "r"(a[0]), "r"(a[1]), "r"(a[2]), "r"(a[3]), "r"(b0), "r"(b1));
}

// ---------------------------------------------------------------------------
// Split fp32 -> fp16 hi + lo (X only)
// ---------------------------------------------------------------------------
__global__ __launch_bounds__(256) void split_kernel(
    const float* __restrict__ x, __half* __restrict__ hi,
    __half* __restrict__ lo)
{
    size_t i = (size_t)blockIdx.x * 256 + threadIdx.x;
    float4 v = ((const float4*)x)[i];
    __half h0 = __float2half_rn(v.x), h1 = __float2half_rn(v.y);
    __half h2 = __float2half_rn(v.z), h3 = __float2half_rn(v.w);
    __half l0 = __float2half_rn(v.x - __half2float(h0));
    __half l1 = __float2half_rn(v.y - __half2float(h1));
    __half l2 = __float2half_rn(v.z - __half2float(h2));
    __half l3 = __float2half_rn(v.w - __half2float(h3));
    __half2 hv0{h0, h1}, hv1{h2, h3}, lv0{l0, l1}, lv1{l2, l3};
    ((__half2*)hi)[i * 2 + 0] = hv0;
    ((__half2*)hi)[i * 2 + 1] = hv1;
    ((__half2*)lo)[i * 2 + 0] = lv0;
    ((__half2*)lo)[i * 2 + 1] = lv1;
}

// ---------------------------------------------------------------------------
// Transpose + split weights: W[K,1024] fp32 -> Wt[rowOff+N][K] fp16 hi/lo
// ---------------------------------------------------------------------------
__global__ __launch_bounds__(256) void transpose_split_kernel(
    const float* __restrict__ W, __half* __restrict__ Th,
    __half* __restrict__ Tl, int rowOff)
{
    __shared__ float t[32][33];
    int x0 = blockIdx.x * 32, y0 = blockIdx.y * 32;
    int tx = threadIdx.x, ty = threadIdx.y;  // (32, 8)
    #pragma unroll
    for (int j = 0; j < 32; j += 8)
        t[ty + j][tx] = W[(size_t)(y0 + ty + j) * D_IN + x0 + tx];
    __syncthreads();
    #pragma unroll
    for (int j = 0; j < 32; j += 8) {
        float v = t[tx][ty + j];
        __half h = __float2half_rn(v);
        size_t o = (size_t)(rowOff + x0 + ty + j) * GK + y0 + tx;
        Th[o] = h;
        Tl[o] = __float2half_rn(v - __half2float(h));
    }
}

// ---------------------------------------------------------------------------
// Pipelined split-fp16 GEMM, branch-free per instantiation.
// NMMA: 3 = AhBh+AlBh+AhBl,  2 = AhBh+AlBh,  1 = AhBh only.
// EPI:  0 = fp32 + bias,  1 = split-fp16 Q/K routing,  2 = Vt-hi transpose.
// ---------------------------------------------------------------------------
#define BK2 32
#define AS2 40
#define MAT_E (128 * AS2)
#define STG_E (4 * MAT_E)
#define GSMEM (2 * STG_E * 2)      // 81920 bytes
#define VT_STR 136

template<int NMMA, int EPI>
__global__ __launch_bounds__(256, 2) void gemm_ld_kernel(
    const __half* __restrict__ Ah_, const __half* __restrict__ Al_,
    const __half* __restrict__ Bh_, const __half* __restrict__ Bl_,
    const float* __restrict__ bias, float* __restrict__ C,
    __half* __restrict__ oQh, __half* __restrict__ oQl,
    __half* __restrict__ oKh, __half* __restrict__ oKl,
    __half* __restrict__ oVth)
{
    extern __shared__ __half smem[];
    const int tid = threadIdx.x;
    const int wid = tid >> 5, lane = tid & 31;
    const int g = lane >> 2, tig = lane & 3;
    const int warpRow = (wid >> 1) * 32;
    const int warpCol = (wid & 1) * 64;
    const int rowBase = blockIdx.y * 128;
    const int colBase = blockIdx.x * 128;

    const __half* gA0 = Ah_ + (size_t)rowBase * GK;
    const __half* gA1 = (NMMA >= 2) ? Al_ + (size_t)rowBase * GK : nullptr;
    const __half* gB0 = Bh_ + (size_t)colBase * GK;
    const __half* gB1 = (NMMA == 3) ? Bl_ + (size_t)colBase * GK : nullptr;

    float acc[2][8][4];
    #pragma unroll
    for (int mt = 0; mt < 2; mt++)
        #pragma unroll
        for (int nt = 0; nt < 8; nt++)
            #pragma unroll
            for (int j = 0; j < 4; j++) acc[mt][nt][j] = 0.f;

    const int lr = tid >> 1, lh = tid & 1;
    const uint32_t sbase = smem_u32(smem);
    const size_t gbase = (size_t)lr * GK + lh * 16;
    const uint32_t sb0 = sbase + (lr * AS2 + lh * 16) * 2;

    const int frow = (lane & 7) + ((lane >> 3) & 1) * 8;
    const int fcol = (lane >> 4) * 8;

    const int NIT = GK / BK2;  // 32

    {
        #pragma unroll
        for (int c = 0; c < 2; c++) {
            cp16(sb0 + c * 16 + 0 * MAT_E * 2, gA0 + gbase + c * 8);
            if (NMMA >= 2) cp16(sb0 + c * 16 + 1 * MAT_E * 2, gA1 + gbase + c * 8);
            cp16(sb0 + c * 16 + 2 * MAT_E * 2, gB0 + gbase + c * 8);
            if (NMMA == 3) cp16(sb0 + c * 16 + 3 * MAT_E * 2, gB1 + gbase + c * 8);
        }
        asm volatile("cp.async.commit_group;" ::: "memory");
    }

    for (int it = 0; it < NIT; it++) {
        if (it + 1 < NIT) {
            const int k0 = (it + 1) * BK2;
            const uint32_t sb = sb0 + ((it + 1) & 1) * STG_E * 2;
            #pragma unroll
            for (int c = 0; c < 2; c++) {
                cp16(sb + c * 16 + 0 * MAT_E * 2, gA0 + gbase + k0 + c * 8);
                if (NMMA >= 2) cp16(sb + c * 16 + 1 * MAT_E * 2, gA1 + gbase + k0 + c * 8);
                cp16(sb + c * 16 + 2 * MAT_E * 2, gB0 + gbase + k0 + c * 8);
                if (NMMA == 3) cp16(sb + c * 16 + 3 * MAT_E * 2, gB1 + gbase + k0 + c * 8);
            }
            asm volatile("cp.async.commit_group;" ::: "memory");
            asm volatile("cp.async.wait_group 1;" ::: "memory");
        } else {
            asm volatile("cp.async.wait_group 0;" ::: "memory");
        }
        __syncthreads();

        const uint32_t stg = sbase + (it & 1) * STG_E * 2;

        #pragma unroll
        for (int ks = 0; ks < 2; ks++) {
            const uint32_t cb = (uint32_t)(ks * 16 + fcol) * 2;
            uint32_t ah[2][4], al[2][4];
            #pragma unroll
            for (int mt = 0; mt < 2; mt++) {
                const uint32_t rb = (uint32_t)(warpRow + mt * 16 + frow) * (AS2 * 2);
                ldsm4(ah[mt], stg + 0 * MAT_E * 2 + rb + cb);
                if (NMMA >= 2) ldsm4(al[mt], stg + 1 * MAT_E * 2 + rb + cb);
            }
            #pragma unroll
            for (int ntp = 0; ntp < 4; ntp++) {
                const uint32_t rb = (uint32_t)(warpCol + ntp * 16 + frow) * (AS2 * 2);
                uint32_t bh4[4];
                ldsm4(bh4, stg + 2 * MAT_E * 2 + rb + cb);
                if (NMMA == 3) {
                    uint32_t bl4[4];
                    ldsm4(bl4, stg + 3 * MAT_E * 2 + rb + cb);
                    #pragma unroll
                    for (int s = 0; s < 2; s++) {
                        const int nt = ntp * 2 + s;
                        #pragma unroll
                        for (int mt = 0; mt < 2; mt++) {
                            mma_f16(acc[mt][nt], ah[mt], bh4[s], bh4[2 + s]);
                            mma_f16(acc[mt][nt], al[mt], bh4[s], bh4[2 + s]);
                            mma_f16(acc[mt][nt], ah[mt], bl4[s], bl4[2 + s]);
                        }
                    }
                } else if (NMMA == 2) {
                    #pragma unroll
                    for (int s = 0; s < 2; s++) {
                        const int nt = ntp * 2 + s;
                        #pragma unroll
                        for (int mt = 0; mt < 2; mt++) {
                            mma_f16(acc[mt][nt], ah[mt], bh4[s], bh4[2 + s]);
                            mma_f16(acc[mt][nt], al[mt], bh4[s], bh4[2 + s]);
                        }
                    }
                } else {
                    #pragma unroll
                    for (int s = 0; s < 2; s++) {
                        const int nt = ntp * 2 + s;
                        #pragma unroll
                        for (int mt = 0; mt < 2; mt++)
                            mma_f16(acc[mt][nt], ah[mt], bh4[s], bh4[2 + s]);
                    }
                }
            }
        }
        __syncthreads();
    }

    // ---------------- epilogue ----------------
    if (EPI == 2) {
        // Vt-hi transpose: write Vt[(b*16+h)*64+d][seq]
        __half* tH = smem;   // [128][VT_STR]
        #pragma unroll
        for (int mt = 0; mt < 2; mt++) {
            #pragma unroll
            for (int nt = 0; nt < 8; nt++) {
                const int cl = warpCol + nt * 8 + tig * 2;
                const int rl = warpRow + mt * 16 + g;
                #pragma unroll
                for (int j = 0; j < 4; j++) {
                    const int c = cl + (j & 1);
                    const int r = rl + (j >> 1) * 8;
                    tH[c * VT_STR + r] = __float2half_rn(acc[mt][nt][j]);
                }
            }
        }
        __syncthreads();
        const int dl = tid >> 1, hf = tid & 1;
        const int bq = rowBase / NSEQ;
        const int seq0 = rowBase & (NSEQ - 1);
        const int h0 = colBase >> 6;
        const size_t orow = ((size_t)(bq * NHEAD + h0) * HDIM + dl) * NSEQ + seq0 + hf * 64;
        const __half* sH = tH + dl * VT_STR + hf * 64;
        #pragma unroll
        for (int u = 0; u < 8; u++)
            *(uint4*)(oVth + orow + u * 8) = *(const uint4*)(sH + u * 8);
        return;
    }

    #pragma unroll
    for (int mt = 0; mt < 2; mt++) {
        #pragma unroll
        for (int nt = 0; nt < 8; nt++) {
            const int r0 = rowBase + warpRow + mt * 16 + g;
            if (EPI == 0) {
                const int col = colBase + warpCol + nt * 8 + tig * 2;
                float bx = bias[col], by = bias[col + 1];
                float2 v0 = {acc[mt][nt][0] + bx, acc[mt][nt][1] + by};
                float2 v1 = {acc[mt][nt][2] + bx, acc[mt][nt][3] + by};
                *(float2*)(C + (size_t)r0 * D_IN + col) = v0;
                *(float2*)(C + (size_t)(r0 + 8) * D_IN + col) = v1;
            } else {
                const int region = colBase >> 10;                  // 0:Q 1:K
                const int col = (colBase & 1023) + warpCol + nt * 8 + tig * 2;
                __half* Ho = (region == 0) ? oQh : oKh;
                __half* Lo = (region == 0) ? oQl : oKl;
                float2 v0 = {acc[mt][nt][0], acc[mt][nt][1]};
                float2 v1 = {acc[mt][nt][2], acc[mt][nt][3]};
                __half2 h0 = __float22half2_rn(v0);
                __half2 h1 = __float22half2_rn(v1);
                __half2 l0 = __float22half2_rn(make_float2(
                    v0.x - __half2float(h0.x), v0.y - __half2float(h0.y)));
                __half2 l1 = __float22half2_rn(make_float2(
                    v1.x - __half2float(h1.x), v1.y - __half2float(h1.y)));
                *(uint32_t*)(Ho + (size_t)r0 * D_IN + col) = *(uint32_t*)&h0;
                *(uint32_t*)(Ho + (size_t)(r0 + 8) * D_IN + col) = *(uint32_t*)&h1;
                *(uint32_t*)(Lo + (size_t)r0 * D_IN + col) = *(uint32_t*)&l0;
                *(uint32_t*)(Lo + (size_t)(r0 + 8) * D_IN + col) = *(uint32_t*)&l1;
            }
        }
    }
}

// ---------------------------------------------------------------------------
// Tensor-core causal flash attention. QK: 3-MMA fp16 split; PV: 1-MMA
// (P hi x V hi). Writes ctx hi only. cp.async double-buffered tiles.
// ---------------------------------------------------------------------------
#define KSTR 72
#define TILE_B2 (64 * KSTR * 2)
#define ASTAGE_B (3 * TILE_B2)
#define ATTN_SMEM2 (2 * ASTAGE_B)        // 55296 bytes
#define EXP_C 0.1803368801111204f        // log2(e)/8

__global__ __launch_bounds__(256) void attn_mma_kernel(
    const __half* __restrict__ Qh, const __half* __restrict__ Ql,
    const __half* __restrict__ Kh, const __half* __restrict__ Kl,
    const __half* __restrict__ Vth, __half* __restrict__ Ch)
{
    extern __shared__ __half asmem[];
    const uint32_t sb = smem_u32(asmem);

    const int tid = threadIdx.x;
    const int wid = tid >> 5, lane = tid & 31;
    const int g = lane >> 2, tig = lane & 3;
    const int q0 = ((int)gridDim.x - 1 - (int)blockIdx.x) * 128;
    const int h = blockIdx.y, b = blockIdx.z;
    const int bh = b * NHEAD + h;
    const int rA = q0 + wid * 16 + g;
    const int rB = rA + 8;

    const size_t qrow = (size_t)(b * NSEQ + q0 + wid * 16) * D_IN + h * HDIM;
    uint32_t qh[4][4], ql[4][4];
    #pragma unroll
    for (int ks = 0; ks < 4; ks++) {
        const int col = ks * 16 + tig * 2;
        qh[ks][0] = *(const uint32_t*)(Qh + qrow + (size_t)g * D_IN + col);
        qh[ks][1] = *(const uint32_t*)(Qh + qrow + (size_t)(g + 8) * D_IN + col);
        qh[ks][2] = *(const uint32_t*)(Qh + qrow + (size_t)g * D_IN + col + 8);
        qh[ks][3] = *(const uint32_t*)(Qh + qrow + (size_t)(g + 8) * D_IN + col + 8);
        ql[ks][0] = *(const uint32_t*)(Ql + qrow + (size_t)g * D_IN + col);
        ql[ks][1] = *(const uint32_t*)(Ql + qrow + (size_t)(g + 8) * D_IN + col);
        ql[ks][2] = *(const uint32_t*)(Ql + qrow + (size_t)g * D_IN + col + 8);
        ql[ks][3] = *(const uint32_t*)(Ql + qrow + (size_t)(g + 8) * D_IN + col + 8);
    }

    float O[8][4];
    #pragma unroll
    for (int nt = 0; nt < 8; nt++)
        #pragma unroll
        for (int j = 0; j < 4; j++) O[nt][j] = 0.f;
    float la = 0.f, lb = 0.f;

    const int ktmax = (q0 + 127) >> 6;
    const int lr = tid >> 3, lc = (tid & 7) * 8;

    auto load_tile = [&](int kt, int stage) {
        const int k0 = kt * 64;
        const uint32_t st = sb + stage * ASTAGE_B;
        #pragma unroll
        for (int i = 0; i < 2; i++) {
            const int r = lr + i * 32;
            const size_t gk = (size_t)(b * NSEQ + k0 + r) * D_IN + h * HDIM + lc;
            const size_t gv = (size_t)(bh * HDIM + r) * NSEQ + k0 + lc;
            const uint32_t so = (uint32_t)(r * KSTR + lc) * 2;
            cp16(st + 0 * TILE_B2 + so, Kh + gk);
            cp16(st + 1 * TILE_B2 + so, Kl + gk);
            cp16(st + 2 * TILE_B2 + so, Vth + gv);
        }
        asm volatile("cp.async.commit_group;" ::: "memory");
    };

    load_tile(0, 0);

    for (int kt = 0; kt <= ktmax; kt++) {
        if (kt < ktmax) {
            load_tile(kt + 1, (kt + 1) & 1);
            asm volatile("cp.async.wait_group 1;" ::: "memory");
        } else {
            asm volatile("cp.async.wait_group 0;" ::: "memory");
        }
        __syncthreads();

        const int k0 = kt * 64;
        const __half* stg = asmem + (kt & 1) * (ASTAGE_B / 2);
        const __half* sKh = stg;
        const __half* sKl = stg + 64 * KSTR;
        const __half* sVh = stg + 2 * 64 * KSTR;

        if (k0 <= q0 + wid * 16 + 15) {
            float S[8][4];
            #pragma unroll
            for (int nt = 0; nt < 8; nt++)
                #pragma unroll
                for (int j = 0; j < 4; j++) S[nt][j] = 0.f;

            #pragma unroll
            for (int ks = 0; ks < 4; ks++) {
                const int koff = ks * 16 + tig * 2;
                #pragma unroll
                for (int nt = 0; nt < 8; nt++) {
                    const int n = nt * 8 + g;
                    uint32_t b0h = *(const uint32_t*)(sKh + n * KSTR + koff);
                    uint32_t b1h = *(const uint32_t*)(sKh + n * KSTR + koff + 8);
                    uint32_t b0l = *(const uint32_t*)(sKl + n * KSTR + koff);
                    uint32_t b1l = *(const uint32_t*)(sKl + n * KSTR + koff + 8);
                    mma_f16(S[nt], qh[ks], b0h, b1h);
                    mma_f16(S[nt], qh[ks], b0l, b1l);
                    mma_f16(S[nt], ql[ks], b0h, b1h);
                }
            }

            uint32_t ph[4][4];
            #pragma unroll
            for (int nt = 0; nt < 8; nt++) {
                const int c0 = k0 + nt * 8 + tig * 2;
                const int c1 = c0 + 1;
                float p0 = (c0 <= rA) ? fexp2(S[nt][0] * EXP_C) : 0.f;
                float p1 = (c1 <= rA) ? fexp2(S[nt][1] * EXP_C) : 0.f;
                float p2 = (c0 <= rB) ? fexp2(S[nt][2] * EXP_C) : 0.f;
                float p3 = (c1 <= rB) ? fexp2(S[nt][3] * EXP_C) : 0.f;
                la += p0 + p1;
                lb += p2 + p3;
                __half2 h01 = __float22half2_rn(make_float2(p0, p1));
                __half2 h23 = __float22half2_rn(make_float2(p2, p3));
                const int ks = nt >> 1, half = (nt & 1) * 2;
                ph[ks][half + 0] = *(uint32_t*)&h01;
                ph[ks][half + 1] = *(uint32_t*)&h23;
            }

            #pragma unroll
            for (int ks = 0; ks < 4; ks++) {
                const int koff = ks * 16 + tig * 2;
                #pragma unroll
                for (int nt = 0; nt < 8; nt++) {
                    const int n = nt * 8 + g;
                    uint32_t b0h = *(const uint32_t*)(sVh + n * KSTR + koff);
                    uint32_t b1h = *(const uint32_t*)(sVh + n * KSTR + koff + 8);
                    mma_f16(O[nt], ph[ks], b0h, b1h);
                }
            }
        }
        __syncthreads();
    }

    la += __shfl_xor_sync(0xFFFFFFFF, la, 1);
    la += __shfl_xor_sync(0xFFFFFFFF, la, 2);
    lb += __shfl_xor_sync(0xFFFFFFFF, lb, 1);
    lb += __shfl_xor_sync(0xFFFFFFFF, lb, 2);
    const float ia = 1.f / la, ib = 1.f / lb;

    #pragma unroll
    for (int nt = 0; nt < 8; nt++) {
        const int col = h * HDIM + nt * 8 + tig * 2;
        __half2 hA = __float22half2_rn(make_float2(O[nt][0] * ia, O[nt][1] * ia));
        __half2 hB = __float22half2_rn(make_float2(O[nt][2] * ib, O[nt][3] * ib));
        *(uint32_t*)(Ch + (size_t)(b * NSEQ + rA) * D_IN + col) = *(uint32_t*)&hA;
        *(uint32_t*)(Ch + (size_t)(b * NSEQ + rB) * D_IN + col) = *(uint32_t*)&hB;
    }
}

// ---------------------------------------------------------------------------
extern "C" void kernel_launch(void* const* d_in, const int* in_sizes, int n_in,
                              void* d_out, int out_size)
{
    const float* X  = (const float*)d_in[0];
    const float* Wq = (const float*)d_in[1];
    const float* Wk = (const float*)d_in[2];
    const float* Wv = (const float*)d_in[3];
    const float* Wo = (const float*)d_in[4];
    const float* bo = (const float*)d_in[5];
    float* out = (float*)d_out;

    __half *pXh, *pXl, *pCh, *pWth, *pWtl;
    __half *pQh, *pQl, *pKh, *pKl, *pVth;
    cudaGetSymbolAddress((void**)&pXh, g_Xh);
    cudaGetSymbolAddress((void**)&pXl, g_Xl);
    cudaGetSymbolAddress((void**)&pCh, g_Ch);
    cudaGetSymbolAddress((void**)&pWth, g_Wth);
    cudaGetSymbolAddress((void**)&pWtl, g_Wtl);
    cudaGetSymbolAddress((void**)&pQh, g_Qh);
    cudaGetSymbolAddress((void**)&pQl, g_Ql);
    cudaGetSymbolAddress((void**)&pKh, g_Kh);
    cudaGetSymbolAddress((void**)&pKl, g_Kl);
    cudaGetSymbolAddress((void**)&pVth, g_Vth);

    static bool attrs_set = false;
    if (!attrs_set) {
        cudaFuncSetAttribute((const void*)gemm_ld_kernel<3, 1>,
                             cudaFuncAttributeMaxDynamicSharedMemorySize, GSMEM);
        cudaFuncSetAttribute((const void*)gemm_ld_kernel<2, 2>,
                             cudaFuncAttributeMaxDynamicSharedMemorySize, GSMEM);
        cudaFuncSetAttribute((const void*)gemm_ld_kernel<1, 0>,
                             cudaFuncAttributeMaxDynamicSharedMemorySize, GSMEM);
        cudaFuncSetAttribute(attn_mma_kernel,
                             cudaFuncAttributeMaxDynamicSharedMemorySize, ATTN_SMEM2);
        attrs_set = true;
    }

    const int splitBlocks = (MTOT * D_IN) / (256 * 4);
    const dim3 trGrid(D_IN / 32, D_IN / 32), trBlk(32, 8);

    split_kernel<<<splitBlocks, 256>>>(X, pXh, pXl);

    transpose_split_kernel<<<trGrid, trBlk>>>(Wq, pWth, pWtl, 0);
    transpose_split_kernel<<<trGrid, trBlk>>>(Wk, pWth, pWtl, 1024);
    transpose_split_kernel<<<trGrid, trBlk>>>(Wv, pWth, pWtl, 2048);

    // QK projections: 3-MMA
    gemm_ld_kernel<3, 1><<<dim3(16, MTOT / 128), 256, GSMEM>>>(
        pXh, pXl, pWth, pWtl, nullptr, nullptr,
        pQh, pQl, pKh, pKl, nullptr);
    // V projection: 2-MMA, Vt-hi transpose epilogue
    gemm_ld_kernel<2, 2><<<dim3(8, MTOT / 128), 256, GSMEM>>>(
        pXh, pXl, pWth + (size_t)2048 * GK, pWtl, nullptr, nullptr,
        nullptr, nullptr, nullptr, nullptr, pVth);

    attn_mma_kernel<<<dim3(NSEQ / 128, NHEAD, BATCH), 256, ATTN_SMEM2>>>(
        pQh, pQl, pKh, pKl, pVth, pCh);

    // output projection: 1-MMA (ctx hi x Wo hi) + bias
    transpose_split_kernel<<<trGrid, trBlk>>>(Wo, pWth, pWtl, 0);
    gemm_ld_kernel<1, 0><<<dim3(8, MTOT / 128), 256, GSMEM>>>(
        pCh, nullptr, pWth, nullptr, bo, out,
        nullptr, nullptr, nullptr, nullptr, nullptr);
}

// round 12
// speedup vs baseline: 2.7008x; 1.5310x over previous
#include <cuda_runtime.h>
#include <cuda_fp16.h>
#include <cstdint>

// Problem constants
#define D_IN   1024
#define NSEQ   2048
#define BATCH  4
#define NHEAD  16
#define HDIM   64
#define MTOT   (BATCH*NSEQ)   // 8192
#define GK     1024

// ---------------------------------------------------------------------------
// Scratch (no cudaMalloc allowed)
// ---------------------------------------------------------------------------
__device__ __half g_Xh[(size_t)MTOT * D_IN];
__device__ __half g_Xl[(size_t)MTOT * D_IN];
__device__ __half g_Ch[(size_t)MTOT * D_IN];            // ctx hi only
__device__ __half g_Wth[(size_t)3 * D_IN * D_IN];       // Wq|Wk|Wv transposed hi (Wo reuses)
__device__ __half g_Qh[(size_t)MTOT * D_IN];
__device__ __half g_Kh[(size_t)MTOT * D_IN];
__device__ __half g_Vth[(size_t)BATCH * NHEAD * HDIM * NSEQ];   // hi only

__device__ __forceinline__ float fexp2(float x) {
    float r;
    asm("ex2.approx.f32 %0, %1;" : "=f"(r) : "f"(x));
    return r;
}
__device__ __forceinline__ uint32_t smem_u32(const void* p) {
    uint32_t a;
    asm("{ .reg .u64 t; cvta.to.shared.u64 t, %1; cvt.u32.u64 %0, t; }" : "=r"(a) : "l"(p));
    return a;
}
__device__ __forceinline__ void cp16(uint32_t saddr, const void* gptr) {
    asm volatile("cp.async.cg.shared.global [%0], [%1], 16;" :: "r"(saddr), "l"(gptr));
}
__device__ __forceinline__ void ldsm4(uint32_t* r, uint32_t saddr) {
    asm volatile("ldmatrix.sync.aligned.m8n8.x4.shared.b16 {%0,%1,%2,%3}, [%4];"
        : "=r"(r[0]), "=r"(r[1]), "=r"(r[2]), "=r"(r[3]) : "r"(saddr));
}
__device__ __forceinline__ void mma_f16(float* c, const uint32_t* a,
                                        uint32_t b0, uint32_t b1)
{
    asm volatile(
        "mma.sync.aligned.m16n8k16.row.col.f32.f16.f16.f32 "
        "{%0,%1,%2,%3}, {%4,%5,%6,%7}, {%8,%9}, {%0,%1,%2,%3};"
        : "+f"(c[0]), "+f"(c[1]), "+f"(c[2]), "+f"(c[3])
        : "r"(a[0]), "r"(a[1]), "r"(a[2]), "r"(a[3]), "r"(b0), "r"(b1));
}

// ---------------------------------------------------------------------------
// Split fp32 -> fp16 hi + lo (X only; Xl feeds V projection)
// ---------------------------------------------------------------------------
__global__ __launch_bounds__(256) void split_kernel(
    const float* __restrict__ x, __half* __restrict__ hi,
    __half* __restrict__ lo)
{
    size_t i = (size_t)blockIdx.x * 256 + threadIdx.x;
    float4 v = ((const float4*)x)[i];
    __half h0 = __float2half_rn(v.x), h1 = __float2half_rn(v.y);
    __half h2 = __float2half_rn(v.z), h3 = __float2half_rn(v.w);
    __half l0 = __float2half_rn(v.x - __half2float(h0));
    __half l1 = __float2half_rn(v.y - __half2float(h1));
    __half l2 = __float2half_rn(v.z - __half2float(h2));
    __half l3 = __float2half_rn(v.w - __half2float(h3));
    __half2 hv0{h0, h1}, hv1{h2, h3}, lv0{l0, l1}, lv1{l2, l3};
    ((__half2*)hi)[i * 2 + 0] = hv0;
    ((__half2*)hi)[i * 2 + 1] = hv1;
    ((__half2*)lo)[i * 2 + 0] = lv0;
    ((__half2*)lo)[i * 2 + 1] = lv1;
}

// ---------------------------------------------------------------------------
// Transpose weights (hi only): W[K,1024] fp32 -> Wt[rowOff+N][K] fp16
// ---------------------------------------------------------------------------
__global__ __launch_bounds__(256) void transpose_h_kernel(
    const float* __restrict__ W, __half* __restrict__ Th, int rowOff)
{
    __shared__ float t[32][33];
    int x0 = blockIdx.x * 32, y0 = blockIdx.y * 32;
    int tx = threadIdx.x, ty = threadIdx.y;  // (32, 8)
    #pragma unroll
    for (int j = 0; j < 32; j += 8)
        t[ty + j][tx] = W[(size_t)(y0 + ty + j) * D_IN + x0 + tx];
    __syncthreads();
    #pragma unroll
    for (int j = 0; j < 32; j += 8)
        Th[(size_t)(rowOff + x0 + ty + j) * GK + y0 + tx] =
            __float2half_rn(t[tx][ty + j]);
}

// ---------------------------------------------------------------------------
// Pipelined fp16 GEMM, branch-free per instantiation.
// NMMA: 2 = AhBh+AlBh,  1 = AhBh only.
// EPI:  0 = fp32 + bias,  1 = fp16-hi Q/K routing,  2 = Vt-hi transpose.
// ---------------------------------------------------------------------------
#define BK2 32
#define AS2 40
#define MAT_E (128 * AS2)
#define STG_E (4 * MAT_E)
#define GSMEM (2 * STG_E * 2)      // 81920 bytes
#define VT_STR 136

template<int NMMA, int EPI>
__global__ __launch_bounds__(256, 2) void gemm_ld_kernel(
    const __half* __restrict__ Ah_, const __half* __restrict__ Al_,
    const __half* __restrict__ Bh_,
    const float* __restrict__ bias, float* __restrict__ C,
    __half* __restrict__ oQh, __half* __restrict__ oKh,
    __half* __restrict__ oVth)
{
    extern __shared__ __half smem[];
    const int tid = threadIdx.x;
    const int wid = tid >> 5, lane = tid & 31;
    const int g = lane >> 2, tig = lane & 3;
    const int warpRow = (wid >> 1) * 32;
    const int warpCol = (wid & 1) * 64;
    const int rowBase = blockIdx.y * 128;
    const int colBase = blockIdx.x * 128;

    const __half* gA0 = Ah_ + (size_t)rowBase * GK;
    const __half* gA1 = (NMMA >= 2) ? Al_ + (size_t)rowBase * GK : nullptr;
    const __half* gB0 = Bh_ + (size_t)colBase * GK;

    float acc[2][8][4];
    #pragma unroll
    for (int mt = 0; mt < 2; mt++)
        #pragma unroll
        for (int nt = 0; nt < 8; nt++)
            #pragma unroll
            for (int j = 0; j < 4; j++) acc[mt][nt][j] = 0.f;

    const int lr = tid >> 1, lh = tid & 1;
    const uint32_t sbase = smem_u32(smem);
    const size_t gbase = (size_t)lr * GK + lh * 16;
    const uint32_t sb0 = sbase + (lr * AS2 + lh * 16) * 2;

    const int frow = (lane & 7) + ((lane >> 3) & 1) * 8;
    const int fcol = (lane >> 4) * 8;

    const int NIT = GK / BK2;  // 32

    {
        #pragma unroll
        for (int c = 0; c < 2; c++) {
            cp16(sb0 + c * 16 + 0 * MAT_E * 2, gA0 + gbase + c * 8);
            if (NMMA >= 2) cp16(sb0 + c * 16 + 1 * MAT_E * 2, gA1 + gbase + c * 8);
            cp16(sb0 + c * 16 + 2 * MAT_E * 2, gB0 + gbase + c * 8);
        }
        asm volatile("cp.async.commit_group;" ::: "memory");
    }

    for (int it = 0; it < NIT; it++) {
        if (it + 1 < NIT) {
            const int k0 = (it + 1) * BK2;
            const uint32_t sb = sb0 + ((it + 1) & 1) * STG_E * 2;
            #pragma unroll
            for (int c = 0; c < 2; c++) {
                cp16(sb + c * 16 + 0 * MAT_E * 2, gA0 + gbase + k0 + c * 8);
                if (NMMA >= 2) cp16(sb + c * 16 + 1 * MAT_E * 2, gA1 + gbase + k0 + c * 8);
                cp16(sb + c * 16 + 2 * MAT_E * 2, gB0 + gbase + k0 + c * 8);
            }
            asm volatile("cp.async.commit_group;" ::: "memory");
            asm volatile("cp.async.wait_group 1;" ::: "memory");
        } else {
            asm volatile("cp.async.wait_group 0;" ::: "memory");
        }
        __syncthreads();

        const uint32_t stg = sbase + (it & 1) * STG_E * 2;

        #pragma unroll
        for (int ks = 0; ks < 2; ks++) {
            const uint32_t cb = (uint32_t)(ks * 16 + fcol) * 2;
            uint32_t ah[2][4], al[2][4];
            #pragma unroll
            for (int mt = 0; mt < 2; mt++) {
                const uint32_t rb = (uint32_t)(warpRow + mt * 16 + frow) * (AS2 * 2);
                ldsm4(ah[mt], stg + 0 * MAT_E * 2 + rb + cb);
                if (NMMA >= 2) ldsm4(al[mt], stg + 1 * MAT_E * 2 + rb + cb);
            }
            #pragma unroll
            for (int ntp = 0; ntp < 4; ntp++) {
                const uint32_t rb = (uint32_t)(warpCol + ntp * 16 + frow) * (AS2 * 2);
                uint32_t bh4[4];
                ldsm4(bh4, stg + 2 * MAT_E * 2 + rb + cb);
                #pragma unroll
                for (int s = 0; s < 2; s++) {
                    const int nt = ntp * 2 + s;
                    #pragma unroll
                    for (int mt = 0; mt < 2; mt++) {
                        mma_f16(acc[mt][nt], ah[mt], bh4[s], bh4[2 + s]);
                        if (NMMA >= 2)
                            mma_f16(acc[mt][nt], al[mt], bh4[s], bh4[2 + s]);
                    }
                }
            }
        }
        __syncthreads();
    }

    // ---------------- epilogue ----------------
    if (EPI == 2) {
        // Vt-hi transpose: write Vt[(b*16+h)*64+d][seq]
        __half* tH = smem;   // [128][VT_STR]
        #pragma unroll
        for (int mt = 0; mt < 2; mt++) {
            #pragma unroll
            for (int nt = 0; nt < 8; nt++) {
                const int cl = warpCol + nt * 8 + tig * 2;
                const int rl = warpRow + mt * 16 + g;
                #pragma unroll
                for (int j = 0; j < 4; j++) {
                    const int c = cl + (j & 1);
                    const int r = rl + (j >> 1) * 8;
                    tH[c * VT_STR + r] = __float2half_rn(acc[mt][nt][j]);
                }
            }
        }
        __syncthreads();
        const int dl = tid >> 1, hf = tid & 1;
        const int bq = rowBase / NSEQ;
        const int seq0 = rowBase & (NSEQ - 1);
        const int h0 = colBase >> 6;
        const size_t orow = ((size_t)(bq * NHEAD + h0) * HDIM + dl) * NSEQ + seq0 + hf * 64;
        const __half* sH = tH + dl * VT_STR + hf * 64;
        #pragma unroll
        for (int u = 0; u < 8; u++)
            *(uint4*)(oVth + orow + u * 8) = *(const uint4*)(sH + u * 8);
        return;
    }

    #pragma unroll
    for (int mt = 0; mt < 2; mt++) {
        #pragma unroll
        for (int nt = 0; nt < 8; nt++) {
            const int r0 = rowBase + warpRow + mt * 16 + g;
            if (EPI == 0) {
                const int col = colBase + warpCol + nt * 8 + tig * 2;
                float bx = bias[col], by = bias[col + 1];
                float2 v0 = {acc[mt][nt][0] + bx, acc[mt][nt][1] + by};
                float2 v1 = {acc[mt][nt][2] + bx, acc[mt][nt][3] + by};
                *(float2*)(C + (size_t)r0 * D_IN + col) = v0;
                *(float2*)(C + (size_t)(r0 + 8) * D_IN + col) = v1;
            } else {
                const int region = colBase >> 10;                  // 0:Q 1:K
                const int col = (colBase & 1023) + warpCol + nt * 8 + tig * 2;
                __half* Ho = (region == 0) ? oQh : oKh;
                __half2 h0 = __float22half2_rn(make_float2(acc[mt][nt][0], acc[mt][nt][1]));
                __half2 h1 = __float22half2_rn(make_float2(acc[mt][nt][2], acc[mt][nt][3]));
                *(uint32_t*)(Ho + (size_t)r0 * D_IN + col) = *(uint32_t*)&h0;
                *(uint32_t*)(Ho + (size_t)(r0 + 8) * D_IN + col) = *(uint32_t*)&h1;
            }
        }
    }
}

// ---------------------------------------------------------------------------
// Tensor-core causal flash attention, plain fp16. S: 1-MMA (Qh Kh);
// PV: 1-MMA (P V). ctx hi only. cp.async double-buffered K/V tiles.
// ---------------------------------------------------------------------------
#define KSTR 72
#define TILE_B2 (64 * KSTR * 2)
#define ASTAGE_B (2 * TILE_B2)
#define ATTN_SMEM2 (2 * ASTAGE_B)        // 36864 bytes
#define EXP_C 0.1803368801111204f        // log2(e)/8

__global__ __launch_bounds__(256) void attn_mma_kernel(
    const __half* __restrict__ Qh, const __half* __restrict__ Kh,
    const __half* __restrict__ Vth, __half* __restrict__ Ch)
{
    extern __shared__ __half asmem[];
    const uint32_t sb = smem_u32(asmem);

    const int tid = threadIdx.x;
    const int wid = tid >> 5, lane = tid & 31;
    const int g = lane >> 2, tig = lane & 3;
    const int q0 = ((int)gridDim.x - 1 - (int)blockIdx.x) * 128;
    const int h = blockIdx.y, b = blockIdx.z;
    const int bh = b * NHEAD + h;
    const int rA = q0 + wid * 16 + g;
    const int rB = rA + 8;

    const size_t qrow = (size_t)(b * NSEQ + q0 + wid * 16) * D_IN + h * HDIM;
    uint32_t qh[4][4];
    #pragma unroll
    for (int ks = 0; ks < 4; ks++) {
        const int col = ks * 16 + tig * 2;
        qh[ks][0] = *(const uint32_t*)(Qh + qrow + (size_t)g * D_IN + col);
        qh[ks][1] = *(const uint32_t*)(Qh + qrow + (size_t)(g + 8) * D_IN + col);
        qh[ks][2] = *(const uint32_t*)(Qh + qrow + (size_t)g * D_IN + col + 8);
        qh[ks][3] = *(const uint32_t*)(Qh + qrow + (size_t)(g + 8) * D_IN + col + 8);
    }

    float O[8][4];
    #pragma unroll
    for (int nt = 0; nt < 8; nt++)
        #pragma unroll
        for (int j = 0; j < 4; j++) O[nt][j] = 0.f;
    float la = 0.f, lb = 0.f;

    const int ktmax = (q0 + 127) >> 6;
    const int lr = tid >> 3, lc = (tid & 7) * 8;

    auto load_tile = [&](int kt, int stage) {
        const int k0 = kt * 64;
        const uint32_t st = sb + stage * ASTAGE_B;
        #pragma unroll
        for (int i = 0; i < 2; i++) {
            const int r = lr + i * 32;
            const size_t gk = (size_t)(b * NSEQ + k0 + r) * D_IN + h * HDIM + lc;
            const size_t gv = (size_t)(bh * HDIM + r) * NSEQ + k0 + lc;
            const uint32_t so = (uint32_t)(r * KSTR + lc) * 2;
            cp16(st + 0 * TILE_B2 + so, Kh + gk);
            cp16(st + 1 * TILE_B2 + so, Vth + gv);
        }
        asm volatile("cp.async.commit_group;" ::: "memory");
    };

    load_tile(0, 0);

    for (int kt = 0; kt <= ktmax; kt++) {
        if (kt < ktmax) {
            load_tile(kt + 1, (kt + 1) & 1);
            asm volatile("cp.async.wait_group 1;" ::: "memory");
        } else {
            asm volatile("cp.async.wait_group 0;" ::: "memory");
        }
        __syncthreads();

        const int k0 = kt * 64;
        const __half* stg = asmem + (kt & 1) * (ASTAGE_B / 2);
        const __half* sKh = stg;
        const __half* sVh = stg + 64 * KSTR;

        if (k0 <= q0 + wid * 16 + 15) {
            float S[8][4];
            #pragma unroll
            for (int nt = 0; nt < 8; nt++)
                #pragma unroll
                for (int j = 0; j < 4; j++) S[nt][j] = 0.f;

            #pragma unroll
            for (int ks = 0; ks < 4; ks++) {
                const int koff = ks * 16 + tig * 2;
                #pragma unroll
                for (int nt = 0; nt < 8; nt++) {
                    const int n = nt * 8 + g;
                    uint32_t b0h = *(const uint32_t*)(sKh + n * KSTR + koff);
                    uint32_t b1h = *(const uint32_t*)(sKh + n * KSTR + koff + 8);
                    mma_f16(S[nt], qh[ks], b0h, b1h);
                }
            }

            uint32_t ph[4][4];
            #pragma unroll
            for (int nt = 0; nt < 8; nt++) {
                const int c0 = k0 + nt * 8 + tig * 2;
                const int c1 = c0 + 1;
                float p0 = (c0 <= rA) ? fexp2(S[nt][0] * EXP_C) : 0.f;
                float p1 = (c1 <= rA) ? fexp2(S[nt][1] * EXP_C) : 0.f;
                float p2 = (c0 <= rB) ? fexp2(S[nt][2] * EXP_C) : 0.f;
                float p3 = (c1 <= rB) ? fexp2(S[nt][3] * EXP_C) : 0.f;
                la += p0 + p1;
                lb += p2 + p3;
                __half2 h01 = __float22half2_rn(make_float2(p0, p1));
                __half2 h23 = __float22half2_rn(make_float2(p2, p3));
                const int ks = nt >> 1, half = (nt & 1) * 2;
                ph[ks][half + 0] = *(uint32_t*)&h01;
                ph[ks][half + 1] = *(uint32_t*)&h23;
            }

            #pragma unroll
            for (int ks = 0; ks < 4; ks++) {
                const int koff = ks * 16 + tig * 2;
                #pragma unroll
                for (int nt = 0; nt < 8; nt++) {
                    const int n = nt * 8 + g;
                    uint32_t b0h = *(const uint32_t*)(sVh + n * KSTR + koff);
                    uint32_t b1h = *(const uint32_t*)(sVh + n * KSTR + koff + 8);
                    mma_f16(O[nt], ph[ks], b0h, b1h);
                }
            }
        }
        __syncthreads();
    }

    la += __shfl_xor_sync(0xFFFFFFFF, la, 1);
    la += __shfl_xor_sync(0xFFFFFFFF, la, 2);
    lb += __shfl_xor_sync(0xFFFFFFFF, lb, 1);
    lb += __shfl_xor_sync(0xFFFFFFFF, lb, 2);
    const float ia = 1.f / la, ib = 1.f / lb;

    #pragma unroll
    for (int nt = 0; nt < 8; nt++) {
        const int col = h * HDIM + nt * 8 + tig * 2;
        __half2 hA = __float22half2_rn(make_float2(O[nt][0] * ia, O[nt][1] * ia));
        __half2 hB = __float22half2_rn(make_float2(O[nt][2] * ib, O[nt][3] * ib));
        *(uint32_t*)(Ch + (size_t)(b * NSEQ + rA) * D_IN + col) = *(uint32_t*)&hA;
        *(uint32_t*)(Ch + (size_t)(b * NSEQ + rB) * D_IN + col) = *(uint32_t*)&hB;
    }
}

// ---------------------------------------------------------------------------
extern "C" void kernel_launch(void* const* d_in, const int* in_sizes, int n_in,
                              void* d_out, int out_size)
{
    const float* X  = (const float*)d_in[0];
    const float* Wq = (const float*)d_in[1];
    const float* Wk = (const float*)d_in[2];
    const float* Wv = (const float*)d_in[3];
    const float* Wo = (const float*)d_in[4];
    const float* bo = (const float*)d_in[5];
    float* out = (float*)d_out;

    __half *pXh, *pXl, *pCh, *pWth, *pQh, *pKh, *pVth;
    cudaGetSymbolAddress((void**)&pXh, g_Xh);
    cudaGetSymbolAddress((void**)&pXl, g_Xl);
    cudaGetSymbolAddress((void**)&pCh, g_Ch);
    cudaGetSymbolAddress((void**)&pWth, g_Wth);
    cudaGetSymbolAddress((void**)&pQh, g_Qh);
    cudaGetSymbolAddress((void**)&pKh, g_Kh);
    cudaGetSymbolAddress((void**)&pVth, g_Vth);

    static bool attrs_set = false;
    if (!attrs_set) {
        cudaFuncSetAttribute((const void*)gemm_ld_kernel<1, 1>,
                             cudaFuncAttributeMaxDynamicSharedMemorySize, GSMEM);
        cudaFuncSetAttribute((const void*)gemm_ld_kernel<2, 2>,
                             cudaFuncAttributeMaxDynamicSharedMemorySize, GSMEM);
        cudaFuncSetAttribute((const void*)gemm_ld_kernel<1, 0>,
                             cudaFuncAttributeMaxDynamicSharedMemorySize, GSMEM);
        cudaFuncSetAttribute(attn_mma_kernel,
                             cudaFuncAttributeMaxDynamicSharedMemorySize, ATTN_SMEM2);
        attrs_set = true;
    }

    const int splitBlocks = (MTOT * D_IN) / (256 * 4);
    const dim3 trGrid(D_IN / 32, D_IN / 32), trBlk(32, 8);

    split_kernel<<<splitBlocks, 256>>>(X, pXh, pXl);

    transpose_h_kernel<<<trGrid, trBlk>>>(Wq, pWth, 0);
    transpose_h_kernel<<<trGrid, trBlk>>>(Wk, pWth, 1024);
    transpose_h_kernel<<<trGrid, trBlk>>>(Wv, pWth, 2048);

    // QK projections: 1-MMA fp16, hi-only outputs
    gemm_ld_kernel<1, 1><<<dim3(16, MTOT / 128), 256, GSMEM>>>(
        pXh, nullptr, pWth, nullptr, nullptr, pQh, pKh, nullptr);
    // V projection: 2-MMA (Xh+Xl vs Wvh), Vt-hi transpose epilogue
    gemm_ld_kernel<2, 2><<<dim3(8, MTOT / 128), 256, GSMEM>>>(
        pXh, pXl, pWth + (size_t)2048 * GK, nullptr, nullptr,
        nullptr, nullptr, pVth);

    attn_mma_kernel<<<dim3(NSEQ / 128, NHEAD, BATCH), 256, ATTN_SMEM2>>>(
        pQh, pKh, pVth, pCh);

    // output projection: 1-MMA (ctx hi x Wo hi) + bias
    transpose_h_kernel<<<trGrid, trBlk>>>(Wo, pWth, 0);
    gemm_ld_kernel<1, 0><<<dim3(8, MTOT / 128), 256, GSMEM>>>(
        pCh, nullptr, pWth, bo, out, nullptr, nullptr, nullptr);
}

// round 13
// speedup vs baseline: 3.0631x; 1.1342x over previous
#include <cuda_runtime.h>
#include <cuda_fp16.h>
#include <cstdint>

// Problem constants
#define D_IN   1024
#define NSEQ   2048
#define BATCH  4
#define NHEAD  16
#define HDIM   64
#define MTOT   (BATCH*NSEQ)   // 8192
#define GK     1024

// ---------------------------------------------------------------------------
// Scratch (no cudaMalloc allowed)
// ---------------------------------------------------------------------------
__device__ __half g_Xh[(size_t)MTOT * D_IN];
__device__ __half g_Ch[(size_t)MTOT * D_IN];            // ctx hi
__device__ __half g_Wth[(size_t)3 * D_IN * D_IN];       // Wq|Wk|Wv transposed (Wo reuses)
__device__ __half g_Qh[(size_t)MTOT * D_IN];
__device__ __half g_Kh[(size_t)MTOT * D_IN];
__device__ __half g_Vth[(size_t)BATCH * NHEAD * HDIM * NSEQ];

__device__ __forceinline__ float fexp2(float x) {
    float r;
    asm("ex2.approx.f32 %0, %1;" : "=f"(r) : "f"(x));
    return r;
}
__device__ __forceinline__ uint32_t smem_u32(const void* p) {
    uint32_t a;
    asm("{ .reg .u64 t; cvta.to.shared.u64 t, %1; cvt.u32.u64 %0, t; }" : "=r"(a) : "l"(p));
    return a;
}
__device__ __forceinline__ void cp16(uint32_t saddr, const void* gptr) {
    asm volatile("cp.async.cg.shared.global [%0], [%1], 16;" :: "r"(saddr), "l"(gptr));
}
__device__ __forceinline__ void ldsm4(uint32_t* r, uint32_t saddr) {
    asm volatile("ldmatrix.sync.aligned.m8n8.x4.shared.b16 {%0,%1,%2,%3}, [%4];"
        : "=r"(r[0]), "=r"(r[1]), "=r"(r[2]), "=r"(r[3]) : "r"(saddr));
}
__device__ __forceinline__ void mma_f16(float* c, const uint32_t* a,
                                        uint32_t b0, uint32_t b1)
{
    asm volatile(
        "mma.sync.aligned.m16n8k16.row.col.f32.f16.f16.f32 "
        "{%0,%1,%2,%3}, {%4,%5,%6,%7}, {%8,%9}, {%0,%1,%2,%3};"
        : "+f"(c[0]), "+f"(c[1]), "+f"(c[2]), "+f"(c[3])
        : "r"(a[0]), "r"(a[1]), "r"(a[2]), "r"(a[3]), "r"(b0), "r"(b1));
}

// ---------------------------------------------------------------------------
// Convert fp32 -> fp16 (X only)
// ---------------------------------------------------------------------------
__global__ __launch_bounds__(256) void conv_kernel(
    const float* __restrict__ x, __half* __restrict__ hi)
{
    size_t i = (size_t)blockIdx.x * 256 + threadIdx.x;
    float4 v = ((const float4*)x)[i];
    __half2 hv0 = __float22half2_rn(make_float2(v.x, v.y));
    __half2 hv1 = __float22half2_rn(make_float2(v.z, v.w));
    ((__half2*)hi)[i * 2 + 0] = hv0;
    ((__half2*)hi)[i * 2 + 1] = hv1;
}

// ---------------------------------------------------------------------------
// Transpose weights: W[K,1024] fp32 -> Wt[rowOff+N][K] fp16
// ---------------------------------------------------------------------------
__global__ __launch_bounds__(256) void transpose_h_kernel(
    const float* __restrict__ W, __half* __restrict__ Th, int rowOff)
{
    __shared__ float t[32][33];
    int x0 = blockIdx.x * 32, y0 = blockIdx.y * 32;
    int tx = threadIdx.x, ty = threadIdx.y;  // (32, 8)
    #pragma unroll
    for (int j = 0; j < 32; j += 8)
        t[ty + j][tx] = W[(size_t)(y0 + ty + j) * D_IN + x0 + tx];
    __syncthreads();
    #pragma unroll
    for (int j = 0; j < 32; j += 8)
        Th[(size_t)(rowOff + x0 + ty + j) * GK + y0 + tx] =
            __float2half_rn(t[tx][ty + j]);
}

// ---------------------------------------------------------------------------
// Pipelined fp16 GEMM (1-MMA), cp.async double-buffered, ldmatrix fragments.
// EPI: 0 = fp32 + bias,  1 = fp16 Q/K routing,  2 = Vt transpose.
// ---------------------------------------------------------------------------
#define BK2 32
#define AS2 40
#define MAT_E (128 * AS2)
#define STG_E (4 * MAT_E)
#define GSMEM (2 * STG_E * 2)      // 81920 bytes
#define VT_STR 136

template<int EPI>
__global__ __launch_bounds__(256, 2) void gemm_ld_kernel(
    const __half* __restrict__ Ah_, const __half* __restrict__ Bh_,
    const float* __restrict__ bias, float* __restrict__ C,
    __half* __restrict__ oQh, __half* __restrict__ oKh,
    __half* __restrict__ oVth)
{
    extern __shared__ __half smem[];
    const int tid = threadIdx.x;
    const int wid = tid >> 5, lane = tid & 31;
    const int g = lane >> 2, tig = lane & 3;
    const int warpRow = (wid >> 1) * 32;
    const int warpCol = (wid & 1) * 64;
    const int rowBase = blockIdx.y * 128;
    const int colBase = blockIdx.x * 128;

    const __half* gA0 = Ah_ + (size_t)rowBase * GK;
    const __half* gB0 = Bh_ + (size_t)colBase * GK;

    float acc[2][8][4];
    #pragma unroll
    for (int mt = 0; mt < 2; mt++)
        #pragma unroll
        for (int nt = 0; nt < 8; nt++)
            #pragma unroll
            for (int j = 0; j < 4; j++) acc[mt][nt][j] = 0.f;

    const int lr = tid >> 1, lh = tid & 1;
    const uint32_t sbase = smem_u32(smem);
    const size_t gbase = (size_t)lr * GK + lh * 16;
    const uint32_t sb0 = sbase + (lr * AS2 + lh * 16) * 2;

    const int frow = (lane & 7) + ((lane >> 3) & 1) * 8;
    const int fcol = (lane >> 4) * 8;

    const int NIT = GK / BK2;  // 32

    {
        #pragma unroll
        for (int c = 0; c < 2; c++) {
            cp16(sb0 + c * 16 + 0 * MAT_E * 2, gA0 + gbase + c * 8);
            cp16(sb0 + c * 16 + 2 * MAT_E * 2, gB0 + gbase + c * 8);
        }
        asm volatile("cp.async.commit_group;" ::: "memory");
    }

    for (int it = 0; it < NIT; it++) {
        if (it + 1 < NIT) {
            const int k0 = (it + 1) * BK2;
            const uint32_t sb = sb0 + ((it + 1) & 1) * STG_E * 2;
            #pragma unroll
            for (int c = 0; c < 2; c++) {
                cp16(sb + c * 16 + 0 * MAT_E * 2, gA0 + gbase + k0 + c * 8);
                cp16(sb + c * 16 + 2 * MAT_E * 2, gB0 + gbase + k0 + c * 8);
            }
            asm volatile("cp.async.commit_group;" ::: "memory");
            asm volatile("cp.async.wait_group 1;" ::: "memory");
        } else {
            asm volatile("cp.async.wait_group 0;" ::: "memory");
        }
        __syncthreads();

        const uint32_t stg = sbase + (it & 1) * STG_E * 2;

        #pragma unroll
        for (int ks = 0; ks < 2; ks++) {
            const uint32_t cb = (uint32_t)(ks * 16 + fcol) * 2;
            uint32_t ah[2][4];
            #pragma unroll
            for (int mt = 0; mt < 2; mt++) {
                const uint32_t rb = (uint32_t)(warpRow + mt * 16 + frow) * (AS2 * 2);
                ldsm4(ah[mt], stg + 0 * MAT_E * 2 + rb + cb);
            }
            #pragma unroll
            for (int ntp = 0; ntp < 4; ntp++) {
                const uint32_t rb = (uint32_t)(warpCol + ntp * 16 + frow) * (AS2 * 2);
                uint32_t bh4[4];
                ldsm4(bh4, stg + 2 * MAT_E * 2 + rb + cb);
                #pragma unroll
                for (int s = 0; s < 2; s++) {
                    const int nt = ntp * 2 + s;
                    #pragma unroll
                    for (int mt = 0; mt < 2; mt++)
                        mma_f16(acc[mt][nt], ah[mt], bh4[s], bh4[2 + s]);
                }
            }
        }
        __syncthreads();
    }

    // ---------------- epilogue ----------------
    if (EPI == 2) {
        __half* tH = smem;   // [128][VT_STR]
        #pragma unroll
        for (int mt = 0; mt < 2; mt++) {
            #pragma unroll
            for (int nt = 0; nt < 8; nt++) {
                const int cl = warpCol + nt * 8 + tig * 2;
                const int rl = warpRow + mt * 16 + g;
                #pragma unroll
                for (int j = 0; j < 4; j++) {
                    const int c = cl + (j & 1);
                    const int r = rl + (j >> 1) * 8;
                    tH[c * VT_STR + r] = __float2half_rn(acc[mt][nt][j]);
                }
            }
        }
        __syncthreads();
        const int dl = tid >> 1, hf = tid & 1;
        const int bq = rowBase / NSEQ;
        const int seq0 = rowBase & (NSEQ - 1);
        const int h0 = colBase >> 6;
        const size_t orow = ((size_t)(bq * NHEAD + h0) * HDIM + dl) * NSEQ + seq0 + hf * 64;
        const __half* sH = tH + dl * VT_STR + hf * 64;
        #pragma unroll
        for (int u = 0; u < 8; u++)
            *(uint4*)(oVth + orow + u * 8) = *(const uint4*)(sH + u * 8);
        return;
    }

    #pragma unroll
    for (int mt = 0; mt < 2; mt++) {
        #pragma unroll
        for (int nt = 0; nt < 8; nt++) {
            const int r0 = rowBase + warpRow + mt * 16 + g;
            if (EPI == 0) {
                const int col = colBase + warpCol + nt * 8 + tig * 2;
                float bx = bias[col], by = bias[col + 1];
                float2 v0 = {acc[mt][nt][0] + bx, acc[mt][nt][1] + by};
                float2 v1 = {acc[mt][nt][2] + bx, acc[mt][nt][3] + by};
                *(float2*)(C + (size_t)r0 * D_IN + col) = v0;
                *(float2*)(C + (size_t)(r0 + 8) * D_IN + col) = v1;
            } else {
                const int region = colBase >> 10;                  // 0:Q 1:K
                const int col = (colBase & 1023) + warpCol + nt * 8 + tig * 2;
                __half* Ho = (region == 0) ? oQh : oKh;
                __half2 h0 = __float22half2_rn(make_float2(acc[mt][nt][0], acc[mt][nt][1]));
                __half2 h1 = __float22half2_rn(make_float2(acc[mt][nt][2], acc[mt][nt][3]));
                *(uint32_t*)(Ho + (size_t)r0 * D_IN + col) = *(uint32_t*)&h0;
                *(uint32_t*)(Ho + (size_t)(r0 + 8) * D_IN + col) = *(uint32_t*)&h1;
            }
        }
    }
}

// ---------------------------------------------------------------------------
// Tensor-core causal flash attention, plain fp16, 2 CTAs/SM.
// ---------------------------------------------------------------------------
#define KSTR 72
#define TILE_B2 (64 * KSTR * 2)
#define ASTAGE_B (2 * TILE_B2)
#define ATTN_SMEM2 (2 * ASTAGE_B)        // 36864 bytes
#define EXP_C 0.1803368801111204f        // log2(e)/8

__global__ __launch_bounds__(256, 2) void attn_mma_kernel(
    const __half* __restrict__ Qh, const __half* __restrict__ Kh,
    const __half* __restrict__ Vth, __half* __restrict__ Ch)
{
    extern __shared__ __half asmem[];
    const uint32_t sb = smem_u32(asmem);

    const int tid = threadIdx.x;
    const int wid = tid >> 5, lane = tid & 31;
    const int g = lane >> 2, tig = lane & 3;
    const int q0 = ((int)gridDim.x - 1 - (int)blockIdx.x) * 128;
    const int h = blockIdx.y, b = blockIdx.z;
    const int bh = b * NHEAD + h;
    const int rA = q0 + wid * 16 + g;
    const int rB = rA + 8;

    const size_t qrow = (size_t)(b * NSEQ + q0 + wid * 16) * D_IN + h * HDIM;
    uint32_t qh[4][4];
    #pragma unroll
    for (int ks = 0; ks < 4; ks++) {
        const int col = ks * 16 + tig * 2;
        qh[ks][0] = *(const uint32_t*)(Qh + qrow + (size_t)g * D_IN + col);
        qh[ks][1] = *(const uint32_t*)(Qh + qrow + (size_t)(g + 8) * D_IN + col);
        qh[ks][2] = *(const uint32_t*)(Qh + qrow + (size_t)g * D_IN + col + 8);
        qh[ks][3] = *(const uint32_t*)(Qh + qrow + (size_t)(g + 8) * D_IN + col + 8);
    }

    float O[8][4];
    #pragma unroll
    for (int nt = 0; nt < 8; nt++)
        #pragma unroll
        for (int j = 0; j < 4; j++) O[nt][j] = 0.f;
    float la = 0.f, lb = 0.f;

    const int ktmax = (q0 + 127) >> 6;
    const int lr = tid >> 3, lc = (tid & 7) * 8;

    auto load_tile = [&](int kt, int stage) {
        const int k0 = kt * 64;
        const uint32_t st = sb + stage * ASTAGE_B;
        #pragma unroll
        for (int i = 0; i < 2; i++) {
            const int r = lr + i * 32;
            const size_t gk = (size_t)(b * NSEQ + k0 + r) * D_IN + h * HDIM + lc;
            const size_t gv = (size_t)(bh * HDIM + r) * NSEQ + k0 + lc;
            const uint32_t so = (uint32_t)(r * KSTR + lc) * 2;
            cp16(st + 0 * TILE_B2 + so, Kh + gk);
            cp16(st + 1 * TILE_B2 + so, Vth + gv);
        }
        asm volatile("cp.async.commit_group;" ::: "memory");
    };

    load_tile(0, 0);

    for (int kt = 0; kt <= ktmax; kt++) {
        if (kt < ktmax) {
            load_tile(kt + 1, (kt + 1) & 1);
            asm volatile("cp.async.wait_group 1;" ::: "memory");
        } else {
            asm volatile("cp.async.wait_group 0;" ::: "memory");
        }
        __syncthreads();

        const int k0 = kt * 64;
        const __half* stg = asmem + (kt & 1) * (ASTAGE_B / 2);
        const __half* sKh = stg;
        const __half* sVh = stg + 64 * KSTR;

        if (k0 <= q0 + wid * 16 + 15) {
            float S[8][4];
            #pragma unroll
            for (int nt = 0; nt < 8; nt++)
                #pragma unroll
                for (int j = 0; j < 4; j++) S[nt][j] = 0.f;

            #pragma unroll
            for (int ks = 0; ks < 4; ks++) {
                const int koff = ks * 16 + tig * 2;
                #pragma unroll
                for (int nt = 0; nt < 8; nt++) {
                    const int n = nt * 8 + g;
                    uint32_t b0h = *(const uint32_t*)(sKh + n * KSTR + koff);
                    uint32_t b1h = *(const uint32_t*)(sKh + n * KSTR + koff + 8);
                    mma_f16(S[nt], qh[ks], b0h, b1h);
                }
            }

            uint32_t ph[4][4];
            #pragma unroll
            for (int nt = 0; nt < 8; nt++) {
                const int c0 = k0 + nt * 8 + tig * 2;
                const int c1 = c0 + 1;
                float p0 = (c0 <= rA) ? fexp2(S[nt][0] * EXP_C) : 0.f;
                float p1 = (c1 <= rA) ? fexp2(S[nt][1] * EXP_C) : 0.f;
                float p2 = (c0 <= rB) ? fexp2(S[nt][2] * EXP_C) : 0.f;
                float p3 = (c1 <= rB) ? fexp2(S[nt][3] * EXP_C) : 0.f;
                la += p0 + p1;
                lb += p2 + p3;
                __half2 h01 = __float22half2_rn(make_float2(p0, p1));
                __half2 h23 = __float22half2_rn(make_float2(p2, p3));
                const int ks = nt >> 1, half = (nt & 1) * 2;
                ph[ks][half + 0] = *(uint32_t*)&h01;
                ph[ks][half + 1] = *(uint32_t*)&h23;
            }

            #pragma unroll
            for (int ks = 0; ks < 4; ks++) {
                const int koff = ks * 16 + tig * 2;
                #pragma unroll
                for (int nt = 0; nt < 8; nt++) {
                    const int n = nt * 8 + g;
                    uint32_t b0h = *(const uint32_t*)(sVh + n * KSTR + koff);
                    uint32_t b1h = *(const uint32_t*)(sVh + n * KSTR + koff + 8);
                    mma_f16(O[nt], ph[ks], b0h, b1h);
                }
            }
        }
        __syncthreads();
    }

    la += __shfl_xor_sync(0xFFFFFFFF, la, 1);
    la += __shfl_xor_sync(0xFFFFFFFF, la, 2);
    lb += __shfl_xor_sync(0xFFFFFFFF, lb, 1);
    lb += __shfl_xor_sync(0xFFFFFFFF, lb, 2);
    const float ia = 1.f / la, ib = 1.f / lb;

    #pragma unroll
    for (int nt = 0; nt < 8; nt++) {
        const int col = h * HDIM + nt * 8 + tig * 2;
        __half2 hA = __float22half2_rn(make_float2(O[nt][0] * ia, O[nt][1] * ia));
        __half2 hB = __float22half2_rn(make_float2(O[nt][2] * ib, O[nt][3] * ib));
        *(uint32_t*)(Ch + (size_t)(b * NSEQ + rA) * D_IN + col) = *(uint32_t*)&hA;
        *(uint32_t*)(Ch + (size_t)(b * NSEQ + rB) * D_IN + col) = *(uint32_t*)&hB;
    }
}

// ---------------------------------------------------------------------------
extern "C" void kernel_launch(void* const* d_in, const int* in_sizes, int n_in,
                              void* d_out, int out_size)
{
    const float* X  = (const float*)d_in[0];
    const float* Wq = (const float*)d_in[1];
    const float* Wk = (const float*)d_in[2];
    const float* Wv = (const float*)d_in[3];
    const float* Wo = (const float*)d_in[4];
    const float* bo = (const float*)d_in[5];
    float* out = (float*)d_out;

    __half *pXh, *pCh, *pWth, *pQh, *pKh, *pVth;
    cudaGetSymbolAddress((void**)&pXh, g_Xh);
    cudaGetSymbolAddress((void**)&pCh, g_Ch);
    cudaGetSymbolAddress((void**)&pWth, g_Wth);
    cudaGetSymbolAddress((void**)&pQh, g_Qh);
    cudaGetSymbolAddress((void**)&pKh, g_Kh);
    cudaGetSymbolAddress((void**)&pVth, g_Vth);

    static bool attrs_set = false;
    if (!attrs_set) {
        cudaFuncSetAttribute((const void*)gemm_ld_kernel<0>,
                             cudaFuncAttributeMaxDynamicSharedMemorySize, GSMEM);
        cudaFuncSetAttribute((const void*)gemm_ld_kernel<1>,
                             cudaFuncAttributeMaxDynamicSharedMemorySize, GSMEM);
        cudaFuncSetAttribute((const void*)gemm_ld_kernel<2>,
                             cudaFuncAttributeMaxDynamicSharedMemorySize, GSMEM);
        cudaFuncSetAttribute(attn_mma_kernel,
                             cudaFuncAttributeMaxDynamicSharedMemorySize, ATTN_SMEM2);
        attrs_set = true;
    }

    const int convBlocks = (MTOT * D_IN) / (256 * 4);
    const dim3 trGrid(D_IN / 32, D_IN / 32), trBlk(32, 8);

    conv_kernel<<<convBlocks, 256>>>(X, pXh);

    transpose_h_kernel<<<trGrid, trBlk>>>(Wq, pWth, 0);
    transpose_h_kernel<<<trGrid, trBlk>>>(Wk, pWth, 1024);
    transpose_h_kernel<<<trGrid, trBlk>>>(Wv, pWth, 2048);

    // QK projections: 1-MMA fp16
    gemm_ld_kernel<1><<<dim3(16, MTOT / 128), 256, GSMEM>>>(
        pXh, pWth, nullptr, nullptr, pQh, pKh, nullptr);
    // V projection: 1-MMA fp16, Vt transpose epilogue
    gemm_ld_kernel<2><<<dim3(8, MTOT / 128), 256, GSMEM>>>(
        pXh, pWth + (size_t)2048 * GK, nullptr, nullptr,
        nullptr, nullptr, pVth);

    attn_mma_kernel<<<dim3(NSEQ / 128, NHEAD, BATCH), 256, ATTN_SMEM2>>>(
        pQh, pKh, pVth, pCh);

    // output projection: 1-MMA + bias
    transpose_h_kernel<<<trGrid, trBlk>>>(Wo, pWth, 0);
    gemm_ld_kernel<0><<<dim3(8, MTOT / 128), 256, GSMEM>>>(
        pCh, pWth, bo, out, nullptr, nullptr, nullptr);
}

// round 14
// speedup vs baseline: 3.1037x; 1.0132x over previous
#include <cuda_runtime.h>
#include <cuda_fp16.h>
#include <cstdint>

// Problem constants
#define D_IN   1024
#define NSEQ   2048
#define BATCH  4
#define NHEAD  16
#define HDIM   64
#define MTOT   (BATCH*NSEQ)   // 8192
#define GK     1024

// ---------------------------------------------------------------------------
// Scratch (no cudaMalloc allowed)
// ---------------------------------------------------------------------------
__device__ __half g_Xh[(size_t)MTOT * D_IN];
__device__ __half g_Ch[(size_t)MTOT * D_IN];            // ctx hi
__device__ __half g_Wth[(size_t)4 * D_IN * D_IN];       // Wq|Wk|Wv|Wo transposed
__device__ __half g_Qh[(size_t)MTOT * D_IN];
__device__ __half g_Kh[(size_t)MTOT * D_IN];
__device__ __half g_Vth[(size_t)BATCH * NHEAD * HDIM * NSEQ];

__device__ __forceinline__ float fexp2(float x) {
    float r;
    asm("ex2.approx.f32 %0, %1;" : "=f"(r) : "f"(x));
    return r;
}
__device__ __forceinline__ uint32_t smem_u32(const void* p) {
    uint32_t a;
    asm("{ .reg .u64 t; cvta.to.shared.u64 t, %1; cvt.u32.u64 %0, t; }" : "=r"(a) : "l"(p));
    return a;
}
__device__ __forceinline__ void cp16(uint32_t saddr, const void* gptr) {
    asm volatile("cp.async.cg.shared.global [%0], [%1], 16;" :: "r"(saddr), "l"(gptr));
}
__device__ __forceinline__ void ldsm4(uint32_t* r, uint32_t saddr) {
    asm volatile("ldmatrix.sync.aligned.m8n8.x4.shared.b16 {%0,%1,%2,%3}, [%4];"
        : "=r"(r[0]), "=r"(r[1]), "=r"(r[2]), "=r"(r[3]) : "r"(saddr));
}
__device__ __forceinline__ void mma_f16(float* c, const uint32_t* a,
                                        uint32_t b0, uint32_t b1)
{
    asm volatile(
        "mma.sync.aligned.m16n8k16.row.col.f32.f16.f16.f32 "
        "{%0,%1,%2,%3}, {%4,%5,%6,%7}, {%8,%9}, {%0,%1,%2,%3};"
        : "+f"(c[0]), "+f"(c[1]), "+f"(c[2]), "+f"(c[3])
        : "r"(a[0]), "r"(a[1]), "r"(a[2]), "r"(a[3]), "r"(b0), "r"(b1));
}

// ---------------------------------------------------------------------------
// Convert fp32 -> fp16 (X only)
// ---------------------------------------------------------------------------
__global__ __launch_bounds__(256) void conv_kernel(
    const float* __restrict__ x, __half* __restrict__ hi)
{
    size_t i = (size_t)blockIdx.x * 256 + threadIdx.x;
    float4 v = ((const float4*)x)[i];
    __half2 hv0 = __float22half2_rn(make_float2(v.x, v.y));
    __half2 hv1 = __float22half2_rn(make_float2(v.z, v.w));
    ((__half2*)hi)[i * 2 + 0] = hv0;
    ((__half2*)hi)[i * 2 + 1] = hv1;
}

// ---------------------------------------------------------------------------
// Batched transpose: z selects Wq/Wk/Wv/Wo -> Wt[z*1024 + N][K] fp16
// ---------------------------------------------------------------------------
__global__ __launch_bounds__(256) void transpose4_kernel(
    const float* __restrict__ W0, const float* __restrict__ W1,
    const float* __restrict__ W2, const float* __restrict__ W3,
    __half* __restrict__ Th)
{
    __shared__ float t[32][33];
    const int z = blockIdx.z;
    const float* W = (z == 0) ? W0 : (z == 1) ? W1 : (z == 2) ? W2 : W3;
    const int rowOff = z * 1024;
    int x0 = blockIdx.x * 32, y0 = blockIdx.y * 32;
    int tx = threadIdx.x, ty = threadIdx.y;  // (32, 8)
    #pragma unroll
    for (int j = 0; j < 32; j += 8)
        t[ty + j][tx] = W[(size_t)(y0 + ty + j) * D_IN + x0 + tx];
    __syncthreads();
    #pragma unroll
    for (int j = 0; j < 32; j += 8)
        Th[(size_t)(rowOff + x0 + ty + j) * GK + y0 + tx] =
            __float2half_rn(t[tx][ty + j]);
}

// ---------------------------------------------------------------------------
// Pipelined fp16 GEMM (1-MMA), cp.async double-buffered, ldmatrix fragments.
// EPI 0: fp32 + bias (out projection).
// EPI 1: fused QKV — epilogue routed by column region (0:Q 1:K 2:V-transpose).
// ---------------------------------------------------------------------------
#define BK2 32
#define AS2 40
#define MAT_E (128 * AS2)
#define STG_E (4 * MAT_E)
#define GSMEM (2 * STG_E * 2)      // 81920 bytes
#define VT_STR 136

template<int EPI>
__global__ __launch_bounds__(256, 2) void gemm_ld_kernel(
    const __half* __restrict__ Ah_, const __half* __restrict__ Bh_,
    const float* __restrict__ bias, float* __restrict__ C,
    __half* __restrict__ oQh, __half* __restrict__ oKh,
    __half* __restrict__ oVth)
{
    extern __shared__ __half smem[];
    const int tid = threadIdx.x;
    const int wid = tid >> 5, lane = tid & 31;
    const int g = lane >> 2, tig = lane & 3;
    const int warpRow = (wid >> 1) * 32;
    const int warpCol = (wid & 1) * 64;
    const int rowBase = blockIdx.y * 128;
    const int colBase = blockIdx.x * 128;

    const __half* gA0 = Ah_ + (size_t)rowBase * GK;
    const __half* gB0 = Bh_ + (size_t)colBase * GK;

    float acc[2][8][4];
    #pragma unroll
    for (int mt = 0; mt < 2; mt++)
        #pragma unroll
        for (int nt = 0; nt < 8; nt++)
            #pragma unroll
            for (int j = 0; j < 4; j++) acc[mt][nt][j] = 0.f;

    const int lr = tid >> 1, lh = tid & 1;
    const uint32_t sbase = smem_u32(smem);
    const size_t gbase = (size_t)lr * GK + lh * 16;
    const uint32_t sb0 = sbase + (lr * AS2 + lh * 16) * 2;

    const int frow = (lane & 7) + ((lane >> 3) & 1) * 8;
    const int fcol = (lane >> 4) * 8;

    const int NIT = GK / BK2;  // 32

    {
        #pragma unroll
        for (int c = 0; c < 2; c++) {
            cp16(sb0 + c * 16 + 0 * MAT_E * 2, gA0 + gbase + c * 8);
            cp16(sb0 + c * 16 + 2 * MAT_E * 2, gB0 + gbase + c * 8);
        }
        asm volatile("cp.async.commit_group;" ::: "memory");
    }

    for (int it = 0; it < NIT; it++) {
        if (it + 1 < NIT) {
            const int k0 = (it + 1) * BK2;
            const uint32_t sb = sb0 + ((it + 1) & 1) * STG_E * 2;
            #pragma unroll
            for (int c = 0; c < 2; c++) {
                cp16(sb + c * 16 + 0 * MAT_E * 2, gA0 + gbase + k0 + c * 8);
                cp16(sb + c * 16 + 2 * MAT_E * 2, gB0 + gbase + k0 + c * 8);
            }
            asm volatile("cp.async.commit_group;" ::: "memory");
            asm volatile("cp.async.wait_group 1;" ::: "memory");
        } else {
            asm volatile("cp.async.wait_group 0;" ::: "memory");
        }
        __syncthreads();

        const uint32_t stg = sbase + (it & 1) * STG_E * 2;

        #pragma unroll
        for (int ks = 0; ks < 2; ks++) {
            const uint32_t cb = (uint32_t)(ks * 16 + fcol) * 2;
            uint32_t ah[2][4];
            #pragma unroll
            for (int mt = 0; mt < 2; mt++) {
                const uint32_t rb = (uint32_t)(warpRow + mt * 16 + frow) * (AS2 * 2);
                ldsm4(ah[mt], stg + 0 * MAT_E * 2 + rb + cb);
            }
            #pragma unroll
            for (int ntp = 0; ntp < 4; ntp++) {
                const uint32_t rb = (uint32_t)(warpCol + ntp * 16 + frow) * (AS2 * 2);
                uint32_t bh4[4];
                ldsm4(bh4, stg + 2 * MAT_E * 2 + rb + cb);
                #pragma unroll
                for (int s = 0; s < 2; s++) {
                    const int nt = ntp * 2 + s;
                    #pragma unroll
                    for (int mt = 0; mt < 2; mt++)
                        mma_f16(acc[mt][nt], ah[mt], bh4[s], bh4[2 + s]);
                }
            }
        }
        __syncthreads();
    }

    // ---------------- epilogue ----------------
    if (EPI == 1) {
        const int region = colBase >> 10;   // 0:Q 1:K 2:V
        if (region == 2) {
            // V region: transpose through smem, write Vt[(b*16+h)*64+d][seq]
            __half* tH = smem;   // [128][VT_STR]
            #pragma unroll
            for (int mt = 0; mt < 2; mt++) {
                #pragma unroll
                for (int nt = 0; nt < 8; nt++) {
                    const int cl = warpCol + nt * 8 + tig * 2;
                    const int rl = warpRow + mt * 16 + g;
                    #pragma unroll
                    for (int j = 0; j < 4; j++) {
                        const int c = cl + (j & 1);
                        const int r = rl + (j >> 1) * 8;
                        tH[c * VT_STR + r] = __float2half_rn(acc[mt][nt][j]);
                    }
                }
            }
            __syncthreads();
            const int dl = tid >> 1, hf = tid & 1;
            const int bq = rowBase / NSEQ;
            const int seq0 = rowBase & (NSEQ - 1);
            const int h0 = (colBase & 1023) >> 6;
            const size_t orow =
                ((size_t)(bq * NHEAD + h0) * HDIM + dl) * NSEQ + seq0 + hf * 64;
            const __half* sH = tH + dl * VT_STR + hf * 64;
            #pragma unroll
            for (int u = 0; u < 8; u++)
                *(uint4*)(oVth + orow + u * 8) = *(const uint4*)(sH + u * 8);
            return;
        }
        __half* Ho = (region == 0) ? oQh : oKh;
        #pragma unroll
        for (int mt = 0; mt < 2; mt++) {
            #pragma unroll
            for (int nt = 0; nt < 8; nt++) {
                const int r0 = rowBase + warpRow + mt * 16 + g;
                const int col = (colBase & 1023) + warpCol + nt * 8 + tig * 2;
                __half2 h0 = __float22half2_rn(make_float2(acc[mt][nt][0], acc[mt][nt][1]));
                __half2 h1 = __float22half2_rn(make_float2(acc[mt][nt][2], acc[mt][nt][3]));
                *(uint32_t*)(Ho + (size_t)r0 * D_IN + col) = *(uint32_t*)&h0;
                *(uint32_t*)(Ho + (size_t)(r0 + 8) * D_IN + col) = *(uint32_t*)&h1;
            }
        }
        return;
    }

    // EPI 0: fp32 + bias
    #pragma unroll
    for (int mt = 0; mt < 2; mt++) {
        #pragma unroll
        for (int nt = 0; nt < 8; nt++) {
            const int r0 = rowBase + warpRow + mt * 16 + g;
            const int col = colBase + warpCol + nt * 8 + tig * 2;
            float bx = bias[col], by = bias[col + 1];
            float2 v0 = {acc[mt][nt][0] + bx, acc[mt][nt][1] + by};
            float2 v1 = {acc[mt][nt][2] + bx, acc[mt][nt][3] + by};
            *(float2*)(C + (size_t)r0 * D_IN + col) = v0;
            *(float2*)(C + (size_t)(r0 + 8) * D_IN + col) = v1;
        }
    }
}

// ---------------------------------------------------------------------------
// Tensor-core causal flash attention, plain fp16, 2 CTAs/SM.
// ---------------------------------------------------------------------------
#define KSTR 72
#define TILE_B2 (64 * KSTR * 2)
#define ASTAGE_B (2 * TILE_B2)
#define ATTN_SMEM2 (2 * ASTAGE_B)        // 36864 bytes
#define EXP_C 0.1803368801111204f        // log2(e)/8

__global__ __launch_bounds__(256, 2) void attn_mma_kernel(
    const __half* __restrict__ Qh, const __half* __restrict__ Kh,
    const __half* __restrict__ Vth, __half* __restrict__ Ch)
{
    extern __shared__ __half asmem[];
    const uint32_t sb = smem_u32(asmem);

    const int tid = threadIdx.x;
    const int wid = tid >> 5, lane = tid & 31;
    const int g = lane >> 2, tig = lane & 3;
    const int q0 = ((int)gridDim.x - 1 - (int)blockIdx.x) * 128;
    const int h = blockIdx.y, b = blockIdx.z;
    const int bh = b * NHEAD + h;
    const int rA = q0 + wid * 16 + g;
    const int rB = rA + 8;

    const size_t qrow = (size_t)(b * NSEQ + q0 + wid * 16) * D_IN + h * HDIM;
    uint32_t qh[4][4];
    #pragma unroll
    for (int ks = 0; ks < 4; ks++) {
        const int col = ks * 16 + tig * 2;
        qh[ks][0] = *(const uint32_t*)(Qh + qrow + (size_t)g * D_IN + col);
        qh[ks][1] = *(const uint32_t*)(Qh + qrow + (size_t)(g + 8) * D_IN + col);
        qh[ks][2] = *(const uint32_t*)(Qh + qrow + (size_t)g * D_IN + col + 8);
        qh[ks][3] = *(const uint32_t*)(Qh + qrow + (size_t)(g + 8) * D_IN + col + 8);
    }

    float O[8][4];
    #pragma unroll
    for (int nt = 0; nt < 8; nt++)
        #pragma unroll
        for (int j = 0; j < 4; j++) O[nt][j] = 0.f;
    float la = 0.f, lb = 0.f;

    const int ktmax = (q0 + 127) >> 6;
    const int lr = tid >> 3, lc = (tid & 7) * 8;

    auto load_tile = [&](int kt, int stage) {
        const int k0 = kt * 64;
        const uint32_t st = sb + stage * ASTAGE_B;
        #pragma unroll
        for (int i = 0; i < 2; i++) {
            const int r = lr + i * 32;
            const size_t gk = (size_t)(b * NSEQ + k0 + r) * D_IN + h * HDIM + lc;
            const size_t gv = (size_t)(bh * HDIM + r) * NSEQ + k0 + lc;
            const uint32_t so = (uint32_t)(r * KSTR + lc) * 2;
            cp16(st + 0 * TILE_B2 + so, Kh + gk);
            cp16(st + 1 * TILE_B2 + so, Vth + gv);
        }
        asm volatile("cp.async.commit_group;" ::: "memory");
    };

    load_tile(0, 0);

    for (int kt = 0; kt <= ktmax; kt++) {
        if (kt < ktmax) {
            load_tile(kt + 1, (kt + 1) & 1);
            asm volatile("cp.async.wait_group 1;" ::: "memory");
        } else {
            asm volatile("cp.async.wait_group 0;" ::: "memory");
        }
        __syncthreads();

        const int k0 = kt * 64;
        const __half* stg = asmem + (kt & 1) * (ASTAGE_B / 2);
        const __half* sKh = stg;
        const __half* sVh = stg + 64 * KSTR;

        if (k0 <= q0 + wid * 16 + 15) {
            float S[8][4];
            #pragma unroll
            for (int nt = 0; nt < 8; nt++)
                #pragma unroll
                for (int j = 0; j < 4; j++) S[nt][j] = 0.f;

            #pragma unroll
            for (int ks = 0; ks < 4; ks++) {
                const int koff = ks * 16 + tig * 2;
                #pragma unroll
                for (int nt = 0; nt < 8; nt++) {
                    const int n = nt * 8 + g;
                    uint32_t b0h = *(const uint32_t*)(sKh + n * KSTR + koff);
                    uint32_t b1h = *(const uint32_t*)(sKh + n * KSTR + koff + 8);
                    mma_f16(S[nt], qh[ks], b0h, b1h);
                }
            }

            uint32_t ph[4][4];
            #pragma unroll
            for (int nt = 0; nt < 8; nt++) {
                const int c0 = k0 + nt * 8 + tig * 2;
                const int c1 = c0 + 1;
                float p0 = (c0 <= rA) ? fexp2(S[nt][0] * EXP_C) : 0.f;
                float p1 = (c1 <= rA) ? fexp2(S[nt][1] * EXP_C) : 0.f;
                float p2 = (c0 <= rB) ? fexp2(S[nt][2] * EXP_C) : 0.f;
                float p3 = (c1 <= rB) ? fexp2(S[nt][3] * EXP_C) : 0.f;
                la += p0 + p1;
                lb += p2 + p3;
                __half2 h01 = __float22half2_rn(make_float2(p0, p1));
                __half2 h23 = __float22half2_rn(make_float2(p2, p3));
                const int ks = nt >> 1, half = (nt & 1) * 2;
                ph[ks][half + 0] = *(uint32_t*)&h01;
                ph[ks][half + 1] = *(uint32_t*)&h23;
            }

            #pragma unroll
            for (int ks = 0; ks < 4; ks++) {
                const int koff = ks * 16 + tig * 2;
                #pragma unroll
                for (int nt = 0; nt < 8; nt++) {
                    const int n = nt * 8 + g;
                    uint32_t b0h = *(const uint32_t*)(sVh + n * KSTR + koff);
                    uint32_t b1h = *(const uint32_t*)(sVh + n * KSTR + koff + 8);
                    mma_f16(O[nt], ph[ks], b0h, b1h);
                }
            }
        }
        __syncthreads();
    }

    la += __shfl_xor_sync(0xFFFFFFFF, la, 1);
    la += __shfl_xor_sync(0xFFFFFFFF, la, 2);
    lb += __shfl_xor_sync(0xFFFFFFFF, lb, 1);
    lb += __shfl_xor_sync(0xFFFFFFFF, lb, 2);
    const float ia = 1.f / la, ib = 1.f / lb;

    #pragma unroll
    for (int nt = 0; nt < 8; nt++) {
        const int col = h * HDIM + nt * 8 + tig * 2;
        __half2 hA = __float22half2_rn(make_float2(O[nt][0] * ia, O[nt][1] * ia));
        __half2 hB = __float22half2_rn(make_float2(O[nt][2] * ib, O[nt][3] * ib));
        *(uint32_t*)(Ch + (size_t)(b * NSEQ + rA) * D_IN + col) = *(uint32_t*)&hA;
        *(uint32_t*)(Ch + (size_t)(b * NSEQ + rB) * D_IN + col) = *(uint32_t*)&hB;
    }
}

// ---------------------------------------------------------------------------
extern "C" void kernel_launch(void* const* d_in, const int* in_sizes, int n_in,
                              void* d_out, int out_size)
{
    const float* X  = (const float*)d_in[0];
    const float* Wq = (const float*)d_in[1];
    const float* Wk = (const float*)d_in[2];
    const float* Wv = (const float*)d_in[3];
    const float* Wo = (const float*)d_in[4];
    const float* bo = (const float*)d_in[5];
    float* out = (float*)d_out;

    __half *pXh, *pCh, *pWth, *pQh, *pKh, *pVth;
    cudaGetSymbolAddress((void**)&pXh, g_Xh);
    cudaGetSymbolAddress((void**)&pCh, g_Ch);
    cudaGetSymbolAddress((void**)&pWth, g_Wth);
    cudaGetSymbolAddress((void**)&pQh, g_Qh);
    cudaGetSymbolAddress((void**)&pKh, g_Kh);
    cudaGetSymbolAddress((void**)&pVth, g_Vth);

    static bool attrs_set = false;
    if (!attrs_set) {
        cudaFuncSetAttribute((const void*)gemm_ld_kernel<0>,
                             cudaFuncAttributeMaxDynamicSharedMemorySize, GSMEM);
        cudaFuncSetAttribute((const void*)gemm_ld_kernel<1>,
                             cudaFuncAttributeMaxDynamicSharedMemorySize, GSMEM);
        cudaFuncSetAttribute(attn_mma_kernel,
                             cudaFuncAttributeMaxDynamicSharedMemorySize, ATTN_SMEM2);
        attrs_set = true;
    }

    const int convBlocks = (MTOT * D_IN) / (256 * 4);

    conv_kernel<<<convBlocks, 256>>>(X, pXh);
    transpose4_kernel<<<dim3(D_IN / 32, D_IN / 32, 4), dim3(32, 8)>>>(
        Wq, Wk, Wv, Wo, pWth);

    // Fused QKV projection: 24 column-tiles (Q:0-7, K:8-15, V:16-23)
    gemm_ld_kernel<1><<<dim3(24, MTOT / 128), 256, GSMEM>>>(
        pXh, pWth, nullptr, nullptr, pQh, pKh, pVth);

    attn_mma_kernel<<<dim3(NSEQ / 128, NHEAD, BATCH), 256, ATTN_SMEM2>>>(
        pQh, pKh, pVth, pCh);

    // output projection: weight region 3 (Wo), fp32 + bias
    gemm_ld_kernel<0><<<dim3(8, MTOT / 128), 256, GSMEM>>>(
        pCh, pWth + (size_t)3072 * GK, bo, out, nullptr, nullptr, nullptr);
}